// round 5
// baseline (speedup 1.0000x reference)
#include <cuda_runtime.h>
#include <math.h>
#include <stdint.h>

// ---------------- problem constants ----------------
#define NMAX 100000
#define EMAX 800000
#define NC 416            // packed GEMM output cols: Q(128) K(128) V(128) S(32)
#define QS_STRIDE 160     // q(128) + skip(32)
#define KV_STRIDE 256     // k(128) + v(128)
#define SCAN_B 1024

// ---------------- scratch (device globals; no allocs allowed) ----------------
__device__ __align__(16) float g_qs[(size_t)NMAX * QS_STRIDE];
__device__ __align__(16) float g_kv[(size_t)NMAX * KV_STRIDE];
__device__ __align__(16) float g_h[(size_t)NMAX * 32];
__device__ __align__(16) float g_Wcat0[128 * NC];
__device__ __align__(16) float g_Wcat1[32 * NC];
__device__ float g_bcat0[NC];
__device__ float g_bcat1[NC];
__device__ int   g_cnt[NMAX];
__device__ int   g_rowptr[NMAX + 1];
__device__ int   g_cursor[NMAX];
__device__ int   g_esrc[EMAX];     // src node id per CSR slot (pre-gathered)
__device__ int   g_bsums[1024];

// ---------------- CSR build ----------------
__global__ void k_zero_cnt(int n) {
    int i = blockIdx.x * blockDim.x + threadIdx.x;
    if (i < n) g_cnt[i] = 0;
}

__global__ void k_hist(const int* __restrict__ dst, int e) {
    int i = blockIdx.x * blockDim.x + threadIdx.x;
    if (i < e) atomicAdd(&g_cnt[dst[i]], 1);
}

__global__ void k_scan1(int n) {
    __shared__ int sm[SCAN_B];
    int i = blockIdx.x * SCAN_B + threadIdx.x;
    int v = (i < n) ? g_cnt[i] : 0;
    sm[threadIdx.x] = v;
    for (int off = 1; off < SCAN_B; off <<= 1) {
        __syncthreads();
        int t = (threadIdx.x >= off) ? sm[threadIdx.x - off] : 0;
        __syncthreads();
        sm[threadIdx.x] += t;
    }
    __syncthreads();
    if (i < n) g_rowptr[i + 1] = sm[threadIdx.x];
    if (threadIdx.x == SCAN_B - 1) g_bsums[blockIdx.x] = sm[SCAN_B - 1];
}

__global__ void k_scan2(int nb) {
    __shared__ int sm[SCAN_B];
    int v = (threadIdx.x < nb) ? g_bsums[threadIdx.x] : 0;
    sm[threadIdx.x] = v;
    for (int off = 1; off < SCAN_B; off <<= 1) {
        __syncthreads();
        int t = (threadIdx.x >= off) ? sm[threadIdx.x - off] : 0;
        __syncthreads();
        sm[threadIdx.x] += t;
    }
    __syncthreads();
    if (threadIdx.x < nb) g_bsums[threadIdx.x] = sm[threadIdx.x] - v; // exclusive
}

// scan3 also derives cursor[i] = rowptr[i+1] - cnt[i], and rowptr[0]=0.
__global__ void k_scan3(int n) {
    int i = blockIdx.x * SCAN_B + threadIdx.x;
    if (i < n) {
        int v = g_rowptr[i + 1] + g_bsums[blockIdx.x];
        g_rowptr[i + 1] = v;
        g_cursor[i] = v - g_cnt[i];
    }
    if (i == 0) g_rowptr[0] = 0;
}

__global__ void k_scatter(const int* __restrict__ src, const int* __restrict__ dst, int e) {
    int i = blockIdx.x * blockDim.x + threadIdx.x;
    if (i < e) {
        int p = atomicAdd(&g_cursor[dst[i]], 1);
        g_esrc[p] = src[i];
    }
}

// ---------------- weight packing: Wcat[K][416] row-major + bias ----------------
__device__ __forceinline__ void pack_one(float* Wdst, float* bdst, int i, int K,
                                         const float* Wq, const float* bq,
                                         const float* Wk, const float* bk,
                                         const float* Wv, const float* bv,
                                         const float* Ws, const float* bs) {
    if (i < K * NC) {
        int k = i / NC, j = i % NC;
        float w;
        if (j < 128)      w = Wq[k * 128 + j];
        else if (j < 256) w = Wk[k * 128 + (j - 128)];
        else if (j < 384) w = Wv[k * 128 + (j - 256)];
        else              w = Ws[k * 32 + (j - 384)];
        Wdst[k * NC + j] = w;
    }
    if (i < NC) {
        float b;
        if (i < 128)      b = bq[i];
        else if (i < 256) b = bk[i - 128];
        else if (i < 384) b = bv[i - 256];
        else              b = bs[i - 384];
        bdst[i] = b;
    }
}

__global__ void k_pack_all(const float* Wq0, const float* bq0, const float* Wk0, const float* bk0,
                           const float* Wv0, const float* bv0, const float* Ws0, const float* bs0,
                           const float* Wq1, const float* bq1, const float* Wk1, const float* bk1,
                           const float* Wv1, const float* bv1, const float* Ws1, const float* bs1) {
    int i = blockIdx.x * blockDim.x + threadIdx.x;
    const int T0 = 128 * NC;
    if (i < T0)
        pack_one(g_Wcat0, g_bcat0, i, 128, Wq0, bq0, Wk0, bk0, Wv0, bv0, Ws0, bs0);
    else
        pack_one(g_Wcat1, g_bcat1, i - T0, 32, Wq1, bq1, Wk1, bk1, Wv1, bv1, Ws1, bs1);
}

// ---------------- TF32 tensor-core GEMM, fragment-major SMEM layout ----------------
// A fragments stored as [mt][kc][lane] -> float4 (thread's 4 mma A-regs contiguous),
// B fragments as [ntg][kc][lane] -> float2. Fragment fetch = LDS.128/LDS.64,
// conflict-free, 2.7x fewer LDS wavefronts than row-major tiles.
__device__ __forceinline__ uint32_t f2tf32(float x) {
    uint32_t r;
    asm("cvt.rna.tf32.f32 %0, %1;" : "=r"(r) : "f"(x));
    return r;
}

__device__ __forceinline__ void mma_tf32(float c[4], uint32_t a0, uint32_t a1, uint32_t a2,
                                         uint32_t a3, uint32_t b0, uint32_t b1) {
    asm volatile(
        "mma.sync.aligned.m16n8k8.row.col.f32.tf32.tf32.f32 "
        "{%0,%1,%2,%3}, {%4,%5,%6,%7}, {%8,%9}, {%0,%1,%2,%3};\n"
        : "+f"(c[0]), "+f"(c[1]), "+f"(c[2]), "+f"(c[3])
        : "r"(a0), "r"(a1), "r"(a2), "r"(a3), "r"(b0), "r"(b1));
}

__device__ __forceinline__ void store2(int row, int c, float v0, float v1) {
    if (c < 128) {
        *(float2*)(g_qs + (size_t)row * QS_STRIDE + c) = make_float2(v0, v1);
    } else if (c < 384) {
        *(float2*)(g_kv + (size_t)row * KV_STRIDE + (c - 128)) = make_float2(v0, v1);
    } else {
        *(float2*)(g_qs + (size_t)row * QS_STRIDE + 128 + (c - 384)) = make_float2(v0, v1);
    }
}

template <int K>
__global__ void __launch_bounds__(256) k_gemm(const float* __restrict__ A_ext, int M) {
    constexpr int KC = K / 8;                   // k-slices
    extern __shared__ float smf[];
    float* biassm = smf;                        // 448 floats
    float* AsF = smf + 448;                     // 8 mt * KC * 32 lanes * 4 floats
    float* BsF = AsF + 8 * KC * 128;            // 8 ntg * KC * 32 lanes * 2 floats
    const bool Lyr1 = (K == 32);
    const float* __restrict__ A = Lyr1 ? g_h : A_ext;
    const float* __restrict__ Wc = Lyr1 ? g_Wcat1 : g_Wcat0;
    const float* __restrict__ bc = Lyr1 ? g_bcat1 : g_bcat0;

    int m0 = blockIdx.x * 128;
    int tid = threadIdx.x;
    int wid = tid >> 5, lane = tid & 31;
    int wm = wid >> 1, wn = wid & 1;            // 4 x 2 warp grid over 128x64
    int gid = lane >> 2, tig = lane & 3;

    for (int i = tid; i < NC; i += 256) biassm[i] = bc[i];

    // ---- load A once, tf32-convert, scatter into fragment layout ----
    constexpr int C4 = K / 4;
#pragma unroll
    for (int t = 0; t < (128 * C4) / 256; ++t) {
        int idx = tid + t * 256;
        int r = idx / C4;
        int c4 = idx % C4;
        int k = c4 * 4;
        float4 v = make_float4(0.f, 0.f, 0.f, 0.f);
        int gr = m0 + r;
        if (gr < M) v = *(const float4*)(A + (size_t)gr * K + k);
        int mt = r >> 4, rr = r & 15;
        int kc = k >> 3;
        int reg = (rr >> 3) + (((k >> 2) & 1) << 1);
        float* base = &AsF[((mt * KC + kc) * 32 + (rr & 7) * 4) * 4 + reg];
        base[0]  = __uint_as_float(f2tf32(v.x));
        base[4]  = __uint_as_float(f2tf32(v.y));
        base[8]  = __uint_as_float(f2tf32(v.z));
        base[12] = __uint_as_float(f2tf32(v.w));
    }
    __syncthreads();

    // ---- N-tile loop (7 tiles of 64 cols; last holds 32 real cols) ----
#pragma unroll 1
    for (int t7 = 0; t7 < 7; ++t7) {
        int n0 = t7 * 64;
        // load B tile [K][64] into fragment layout
#pragma unroll
        for (int u = 0; u < (K * 16) / 256; ++u) {
            int idx = tid + u * 256;
            int r = idx >> 4;                   // k row
            int c4 = (idx & 15) << 2;           // col base (0..60)
            int gc = n0 + c4;
            float4 v = make_float4(0.f, 0.f, 0.f, 0.f);
            if (gc < NC) v = *(const float4*)(Wc + (size_t)r * NC + gc);
            int kc = r >> 3;
            int kcol = r & 7;
            int btig = kcol & 3;
            int breg = kcol >> 2;
            int ntg = c4 >> 3;
            int g0 = c4 & 7;
            float* base = &BsF[((ntg * KC + kc) * 32 + g0 * 4 + btig) * 2 + breg];
            base[0]  = __uint_as_float(f2tf32(v.x));
            base[8]  = __uint_as_float(f2tf32(v.y));
            base[16] = __uint_as_float(f2tf32(v.z));
            base[24] = __uint_as_float(f2tf32(v.w));
        }
        __syncthreads();

        float acc[2][4][4];
#pragma unroll
        for (int a = 0; a < 2; ++a)
#pragma unroll
            for (int nt = 0; nt < 4; ++nt)
#pragma unroll
                for (int j = 0; j < 4; ++j) acc[a][nt][j] = 0.f;

#pragma unroll
        for (int kc = 0; kc < KC; ++kc) {
            float4 av[2];
#pragma unroll
            for (int q = 0; q < 2; ++q)
                av[q] = *(const float4*)&AsF[(((wm * 2 + q) * KC + kc) * 32 + lane) * 4];
            float2 bv[4];
#pragma unroll
            for (int nt = 0; nt < 4; ++nt)
                bv[nt] = *(const float2*)&BsF[(((wn * 4 + nt) * KC + kc) * 32 + lane) * 2];
#pragma unroll
            for (int q = 0; q < 2; ++q)
#pragma unroll
                for (int nt = 0; nt < 4; ++nt)
                    mma_tf32(acc[q][nt],
                             __float_as_uint(av[q].x), __float_as_uint(av[q].y),
                             __float_as_uint(av[q].z), __float_as_uint(av[q].w),
                             __float_as_uint(bv[nt].x), __float_as_uint(bv[nt].y));
        }

        // epilogue for this tile
#pragma unroll
        for (int q = 0; q < 2; ++q) {
            int r0 = m0 + wm * 32 + q * 16 + gid;
#pragma unroll
            for (int nt = 0; nt < 4; ++nt) {
                int c = n0 + wn * 32 + nt * 8 + tig * 2;
                if (c >= NC) continue;
                float b0v = biassm[c], b1v = biassm[c + 1];
                if (r0 < M)      store2(r0,     c, acc[q][nt][0] + b0v, acc[q][nt][1] + b1v);
                if (r0 + 8 < M)  store2(r0 + 8, c, acc[q][nt][2] + b0v, acc[q][nt][3] + b1v);
            }
        }
        __syncthreads();   // BsF reused next tile
    }
}

// ---------------- attention: warp per destination node, online softmax ----------------
__global__ void k_attn(int n) {
    int gw = (blockIdx.x * blockDim.x + threadIdx.x) >> 5;
    if (gw >= n) return;
    int lane = threadIdx.x & 31;
    int g = lane >> 3, l = lane & 7;
    int off = g * 32 + l * 4;
    const float scale = 0.17677669529663687f;  // 1/sqrt(32)

    float4 q = *(const float4*)(g_qs + (size_t)gw * QS_STRIDE + off);
    float m = -1e30f, ssum = 0.f;
    float ax = 0.f, ay = 0.f, az = 0.f, aw = 0.f;

    int beg = g_rowptr[gw], end = g_rowptr[gw + 1];

    float4 kc = make_float4(0, 0, 0, 0), vc = make_float4(0, 0, 0, 0);
    int sA = 0;
    if (beg < end) {
        int s0 = __ldg(g_esrc + beg);
        const float* kb = g_kv + (size_t)s0 * KV_STRIDE + off;
        kc = *(const float4*)kb;
        vc = *(const float4*)(kb + 128);
        if (beg + 1 < end) sA = __ldg(g_esrc + beg + 1);
    }

    for (int i = beg; i < end; ++i) {
        int sN = sA;
        if (i + 2 < end) sA = __ldg(g_esrc + i + 2);
        float4 kN = make_float4(0, 0, 0, 0), vN = kN;
        if (i + 1 < end) {
            const float* kb = g_kv + (size_t)sN * KV_STRIDE + off;
            kN = *(const float4*)kb;
            vN = *(const float4*)(kb + 128);
        }

        float d = q.x * kc.x + q.y * kc.y + q.z * kc.z + q.w * kc.w;
        d += __shfl_xor_sync(0xffffffffu, d, 1);
        d += __shfl_xor_sync(0xffffffffu, d, 2);
        d += __shfl_xor_sync(0xffffffffu, d, 4);
        float alpha = d * scale;
        if (alpha > m) {
            float sc = __expf(m - alpha);
            ssum = ssum * sc + 1.f;
            ax = ax * sc + vc.x;
            ay = ay * sc + vc.y;
            az = az * sc + vc.z;
            aw = aw * sc + vc.w;
            m = alpha;
        } else {
            float p = __expf(alpha - m);
            ssum += p;
            ax += p * vc.x;
            ay += p * vc.y;
            az += p * vc.z;
            aw += p * vc.w;
        }
        kc = kN; vc = vN;
    }
    float inv = (ssum > 0.f) ? (1.f / ssum) : 0.f;
    ax *= inv; ay *= inv; az *= inv; aw *= inv;

    ax += __shfl_xor_sync(0xffffffffu, ax, 8);
    ay += __shfl_xor_sync(0xffffffffu, ay, 8);
    az += __shfl_xor_sync(0xffffffffu, az, 8);
    aw += __shfl_xor_sync(0xffffffffu, aw, 8);
    ax += __shfl_xor_sync(0xffffffffu, ax, 16);
    ay += __shfl_xor_sync(0xffffffffu, ay, 16);
    az += __shfl_xor_sync(0xffffffffu, az, 16);
    aw += __shfl_xor_sync(0xffffffffu, aw, 16);

    if (lane < 8) {
        float4 sk = *(const float4*)(g_qs + (size_t)gw * QS_STRIDE + 128 + l * 4);
        float4 o;
        o.x = fmaxf(ax * 0.25f + sk.x, 0.f);
        o.y = fmaxf(ay * 0.25f + sk.y, 0.f);
        o.z = fmaxf(az * 0.25f + sk.z, 0.f);
        o.w = fmaxf(aw * 0.25f + sk.w, 0.f);
        *(float4*)(g_h + (size_t)gw * 32 + l * 4) = o;
    }
}

// ---------------- output projection: out[n,16] = h[n,32] @ Wout + bout ----------------
__global__ void __launch_bounds__(256) k_outproj(const float* __restrict__ Wout,
                                                 const float* __restrict__ bout,
                                                 float* __restrict__ out, int n) {
    __shared__ float Hs[128 * 32];
    __shared__ float Ws[512];
    __shared__ float Bs2[16];
    int node0 = blockIdx.x * 128;
    for (int i = threadIdx.x; i < 512; i += 256) Ws[i] = Wout[i];
    if (threadIdx.x < 16) Bs2[threadIdx.x] = bout[threadIdx.x];
    for (int i = threadIdx.x; i < 128 * 32; i += 256) {
        int r = node0 + (i >> 5);
        Hs[i] = (r < n) ? g_h[(size_t)node0 * 32 + i] : 0.f;
    }
    __syncthreads();
#pragma unroll
    for (int t = 0; t < 8; ++t) {
        int oi = threadIdx.x + t * 256;
        int ln = oi >> 4;
        int j = oi & 15;
        int node = node0 + ln;
        if (node >= n) continue;
        float acc = Bs2[j];
#pragma unroll
        for (int k = 0; k < 32; ++k) acc += Hs[ln * 32 + k] * Ws[k * 16 + j];
        out[(size_t)node * 16 + j] = acc;
    }
}

// ---------------- launch ----------------
extern "C" void kernel_launch(void* const* d_in, const int* in_sizes, int n_in,
                              void* d_out, int out_size) {
    const float* x = (const float*)d_in[0];
    const int*   ei = (const int*)d_in[1];
    int n = in_sizes[0] / 128;
    int e = in_sizes[1] / 2;
    const int* srcp = ei;
    const int* dstp = ei + e;

    const int smem0 = (448 + 8 * 16 * 128 + 8 * 16 * 64) * 4;  // K=128: ~98 KB
    const int smem1 = (448 + 8 * 4 * 128 + 8 * 4 * 64) * 4;    // K=32:  ~26 KB
    cudaFuncSetAttribute(k_gemm<128>, cudaFuncAttributeMaxDynamicSharedMemorySize, smem0);
    cudaFuncSetAttribute(k_gemm<32>,  cudaFuncAttributeMaxDynamicSharedMemorySize, smem1);

    int nb = (n + 255) / 256;
    int eb = (e + 255) / 256;
    int sblocks = (n + SCAN_B - 1) / SCAN_B;
    int gemm_blocks = (n + 127) / 128;
    int attn_blocks = (n + 7) / 8;
    int pack_total = 128 * NC + 32 * NC;

    // launch order keeps the L0 GEMM in the ncu capture slot (4th launch)
    k_pack_all<<<(pack_total + 255) / 256, 256>>>(
        (const float*)d_in[2],  (const float*)d_in[3],
        (const float*)d_in[4],  (const float*)d_in[5],
        (const float*)d_in[6],  (const float*)d_in[7],
        (const float*)d_in[8],  (const float*)d_in[9],
        (const float*)d_in[10], (const float*)d_in[11],
        (const float*)d_in[12], (const float*)d_in[13],
        (const float*)d_in[14], (const float*)d_in[15],
        (const float*)d_in[16], (const float*)d_in[17]);
    k_zero_cnt<<<nb, 256>>>(n);
    k_hist<<<eb, 256>>>(dstp, e);
    k_gemm<128><<<gemm_blocks, 256, smem0>>>(x, n);        // <- profiled slot
    k_scan1<<<sblocks, SCAN_B>>>(n);
    k_scan2<<<1, SCAN_B>>>(sblocks);
    k_scan3<<<sblocks, SCAN_B>>>(n);
    k_scatter<<<eb, 256>>>(srcp, dstp, e);
    k_attn<<<attn_blocks, 256>>>(n);
    k_gemm<32><<<gemm_blocks, 256, smem1>>>(nullptr, n);
    k_attn<<<attn_blocks, 256>>>(n);
    k_outproj<<<(n + 127) / 128, 256>>>(
        (const float*)d_in[18], (const float*)d_in[19], (float*)d_out, n);
}

// round 6
// speedup vs baseline: 1.2070x; 1.2070x over previous
#include <cuda_runtime.h>
#include <math.h>
#include <stdint.h>

// ---------------- problem constants ----------------
#define NMAX 100000
#define EMAX 800000
#define NC 416            // packed GEMM output cols: Q(128) K(128) V(128) S(32)
#define QS_STRIDE 160     // q(128) + skip(32)
#define KV_STRIDE 256     // k(128) + v(128)
#define SCAN_B 1024

// ---------------- scratch (device globals; no allocs allowed) ----------------
__device__ __align__(16) float g_qs[(size_t)NMAX * QS_STRIDE];
__device__ __align__(16) float g_kv[(size_t)NMAX * KV_STRIDE];
__device__ __align__(16) float g_h[(size_t)NMAX * 32];
__device__ __align__(16) float g_Wcat0[128 * NC];
__device__ __align__(16) float g_Wcat1[32 * NC];
__device__ float g_bcat0[NC];
__device__ float g_bcat1[NC];
__device__ int   g_cnt[NMAX];
__device__ int   g_rowptr[NMAX + 1];
__device__ int   g_cursor[NMAX];
__device__ int   g_esrc[EMAX];     // src node id per CSR slot (pre-gathered)
__device__ int   g_bsums[1024];

// ---------------- CSR build ----------------
__global__ void k_zero_cnt(int n) {
    int i = blockIdx.x * blockDim.x + threadIdx.x;
    if (i < n) g_cnt[i] = 0;
}

__global__ void k_hist(const int* __restrict__ dst, int e) {
    int i = blockIdx.x * blockDim.x + threadIdx.x;
    if (i < e) atomicAdd(&g_cnt[dst[i]], 1);
}

__global__ void k_scan1(int n) {
    __shared__ int sm[SCAN_B];
    int i = blockIdx.x * SCAN_B + threadIdx.x;
    int v = (i < n) ? g_cnt[i] : 0;
    sm[threadIdx.x] = v;
    for (int off = 1; off < SCAN_B; off <<= 1) {
        __syncthreads();
        int t = (threadIdx.x >= off) ? sm[threadIdx.x - off] : 0;
        __syncthreads();
        sm[threadIdx.x] += t;
    }
    __syncthreads();
    if (i < n) g_rowptr[i + 1] = sm[threadIdx.x];
    if (threadIdx.x == SCAN_B - 1) g_bsums[blockIdx.x] = sm[SCAN_B - 1];
}

__global__ void k_scan2(int nb) {
    __shared__ int sm[SCAN_B];
    int v = (threadIdx.x < nb) ? g_bsums[threadIdx.x] : 0;
    sm[threadIdx.x] = v;
    for (int off = 1; off < SCAN_B; off <<= 1) {
        __syncthreads();
        int t = (threadIdx.x >= off) ? sm[threadIdx.x - off] : 0;
        __syncthreads();
        sm[threadIdx.x] += t;
    }
    __syncthreads();
    if (threadIdx.x < nb) g_bsums[threadIdx.x] = sm[threadIdx.x] - v; // exclusive
}

// scan3 also derives cursor[i] = rowptr[i+1] - cnt[i], and rowptr[0]=0.
__global__ void k_scan3(int n) {
    int i = blockIdx.x * SCAN_B + threadIdx.x;
    if (i < n) {
        int v = g_rowptr[i + 1] + g_bsums[blockIdx.x];
        g_rowptr[i + 1] = v;
        g_cursor[i] = v - g_cnt[i];
    }
    if (i == 0) g_rowptr[0] = 0;
}

__global__ void k_scatter(const int* __restrict__ src, const int* __restrict__ dst, int e) {
    int i = blockIdx.x * blockDim.x + threadIdx.x;
    if (i < e) {
        int p = atomicAdd(&g_cursor[dst[i]], 1);
        g_esrc[p] = src[i];
    }
}

// ---------------- weight packing: Wcat[K][416] row-major + bias ----------------
__device__ __forceinline__ void pack_one(float* Wdst, float* bdst, int i, int K,
                                         const float* Wq, const float* bq,
                                         const float* Wk, const float* bk,
                                         const float* Wv, const float* bv,
                                         const float* Ws, const float* bs) {
    if (i < K * NC) {
        int k = i / NC, j = i % NC;
        float w;
        if (j < 128)      w = Wq[k * 128 + j];
        else if (j < 256) w = Wk[k * 128 + (j - 128)];
        else if (j < 384) w = Wv[k * 128 + (j - 256)];
        else              w = Ws[k * 32 + (j - 384)];
        Wdst[k * NC + j] = w;
    }
    if (i < NC) {
        float b;
        if (i < 128)      b = bq[i];
        else if (i < 256) b = bk[i - 128];
        else if (i < 384) b = bv[i - 256];
        else              b = bs[i - 384];
        bdst[i] = b;
    }
}

__global__ void k_pack_all(const float* Wq0, const float* bq0, const float* Wk0, const float* bk0,
                           const float* Wv0, const float* bv0, const float* Ws0, const float* bs0,
                           const float* Wq1, const float* bq1, const float* Wk1, const float* bk1,
                           const float* Wv1, const float* bv1, const float* Ws1, const float* bs1) {
    int i = blockIdx.x * blockDim.x + threadIdx.x;
    const int T0 = 128 * NC;
    if (i < T0)
        pack_one(g_Wcat0, g_bcat0, i, 128, Wq0, bq0, Wk0, bk0, Wv0, bv0, Ws0, bs0);
    else
        pack_one(g_Wcat1, g_bcat1, i - T0, 32, Wq1, bq1, Wk1, bk1, Wv1, bv1, Ws1, bs1);
}

// ---------------- TF32 tensor-core GEMM ----------------
// Block tile 128x128 (4 N-tiles over NC=416), 8 warps in 4x2 grid,
// warp tile 32x64 (mt=2, nt=8): A fragments reused across 8 n-subtiles.
// Strides: As (K+4) -> mod32=4, conflict-free A loads; Bs 136 -> mod32=8,
// conflict-free B loads. LDS cycles per warp per kc: 8(A)+16(B) for 16 MMAs.
__device__ __forceinline__ uint32_t f2tf32(float x) {
    uint32_t r;
    asm("cvt.rna.tf32.f32 %0, %1;" : "=r"(r) : "f"(x));
    return r;
}

__device__ __forceinline__ void mma_tf32(float c[4], uint32_t a0, uint32_t a1, uint32_t a2,
                                         uint32_t a3, uint32_t b0, uint32_t b1) {
    asm volatile(
        "mma.sync.aligned.m16n8k8.row.col.f32.tf32.tf32.f32 "
        "{%0,%1,%2,%3}, {%4,%5,%6,%7}, {%8,%9}, {%0,%1,%2,%3};\n"
        : "+f"(c[0]), "+f"(c[1]), "+f"(c[2]), "+f"(c[3])
        : "r"(a0), "r"(a1), "r"(a2), "r"(a3), "r"(b0), "r"(b1));
}

__device__ __forceinline__ void store2(int row, int c, float v0, float v1) {
    if (c < 128) {
        *(float2*)(g_qs + (size_t)row * QS_STRIDE + c) = make_float2(v0, v1);
    } else if (c < 384) {
        *(float2*)(g_kv + (size_t)row * KV_STRIDE + (c - 128)) = make_float2(v0, v1);
    } else {
        *(float2*)(g_qs + (size_t)row * QS_STRIDE + 128 + (c - 384)) = make_float2(v0, v1);
    }
}

template <int K>
__global__ void __launch_bounds__(256) k_gemm(const float* __restrict__ A_ext, int M) {
    constexpr int KC = K / 8;                   // k-slices
    constexpr int AS = K + 4;                   // As row stride
    constexpr int BS = 136;                     // Bs row stride (128 cols used)
    extern __shared__ float smf[];
    float* biassm = smf;                        // 448 floats
    float* As = smf + 448;                      // 128 x AS
    float* Bs = As + 128 * AS;                  // K x BS
    const bool Lyr1 = (K == 32);
    const float* __restrict__ A = Lyr1 ? g_h : A_ext;
    const float* __restrict__ Wc = Lyr1 ? g_Wcat1 : g_Wcat0;
    const float* __restrict__ bc = Lyr1 ? g_bcat1 : g_bcat0;

    int m0 = blockIdx.x * 128;
    int tid = threadIdx.x;
    int wid = tid >> 5, lane = tid & 31;
    int wm = wid >> 1, wn = wid & 1;            // 4 x 2 warp grid over 128x128
    int gid = lane >> 2, tig = lane & 3;

    for (int i = tid; i < NC; i += 256) biassm[i] = bc[i];

    // ---- load A once, tf32-converted ----
    constexpr int C4 = K / 4;
#pragma unroll
    for (int t = 0; t < (128 * C4) / 256; ++t) {
        int idx = tid + t * 256;
        int r = idx / C4;
        int c4 = idx % C4;
        float4 v = make_float4(0.f, 0.f, 0.f, 0.f);
        int gr = m0 + r;
        if (gr < M) v = *(const float4*)(A + (size_t)gr * K + c4 * 4);
        float4 o;
        o.x = __uint_as_float(f2tf32(v.x));
        o.y = __uint_as_float(f2tf32(v.y));
        o.z = __uint_as_float(f2tf32(v.z));
        o.w = __uint_as_float(f2tf32(v.w));
        *(float4*)&As[r * AS + c4 * 4] = o;
    }
    __syncthreads();

    // ---- N-tile loop: 4 tiles of 128 cols (last holds 32 real cols) ----
#pragma unroll 1
    for (int t4 = 0; t4 < 4; ++t4) {
        int n0 = t4 * 128;
        // load B tile [K][128] (tf32-converted)
#pragma unroll
        for (int u = 0; u < (K * 32) / 256; ++u) {
            int idx = tid + u * 256;
            int r = idx >> 5;                   // k row
            int c4 = (idx & 31) << 2;           // col 0..124
            int gc = n0 + c4;
            float4 v = make_float4(0.f, 0.f, 0.f, 0.f);
            if (gc < NC) v = *(const float4*)(Wc + (size_t)r * NC + gc);
            float4 o;
            o.x = __uint_as_float(f2tf32(v.x));
            o.y = __uint_as_float(f2tf32(v.y));
            o.z = __uint_as_float(f2tf32(v.z));
            o.w = __uint_as_float(f2tf32(v.w));
            *(float4*)&Bs[r * BS + c4] = o;
        }
        __syncthreads();

        float acc[2][8][4];
#pragma unroll
        for (int q = 0; q < 2; ++q)
#pragma unroll
            for (int nt = 0; nt < 8; ++nt)
#pragma unroll
                for (int j = 0; j < 4; ++j) acc[q][nt][j] = 0.f;

#pragma unroll
        for (int kc = 0; kc < KC; ++kc) {
            int kk = kc * 8;
            uint32_t a[2][4];
#pragma unroll
            for (int q = 0; q < 2; ++q) {
                int rb = wm * 32 + q * 16;
                a[q][0] = __float_as_uint(As[(rb + gid) * AS + kk + tig]);
                a[q][1] = __float_as_uint(As[(rb + gid + 8) * AS + kk + tig]);
                a[q][2] = __float_as_uint(As[(rb + gid) * AS + kk + tig + 4]);
                a[q][3] = __float_as_uint(As[(rb + gid + 8) * AS + kk + tig + 4]);
            }
            uint32_t b[8][2];
#pragma unroll
            for (int nt = 0; nt < 8; ++nt) {
                int col = wn * 64 + nt * 8 + gid;
                b[nt][0] = __float_as_uint(Bs[(kk + tig) * BS + col]);
                b[nt][1] = __float_as_uint(Bs[(kk + tig + 4) * BS + col]);
            }
#pragma unroll
            for (int q = 0; q < 2; ++q)
#pragma unroll
                for (int nt = 0; nt < 8; ++nt)
                    mma_tf32(acc[q][nt], a[q][0], a[q][1], a[q][2], a[q][3],
                             b[nt][0], b[nt][1]);
        }

        // epilogue for this tile
#pragma unroll
        for (int q = 0; q < 2; ++q) {
            int r0 = m0 + wm * 32 + q * 16 + gid;
#pragma unroll
            for (int nt = 0; nt < 8; ++nt) {
                int c = n0 + wn * 64 + nt * 8 + tig * 2;
                if (c >= NC) continue;
                float b0v = biassm[c], b1v = biassm[c + 1];
                if (r0 < M)      store2(r0,     c, acc[q][nt][0] + b0v, acc[q][nt][1] + b1v);
                if (r0 + 8 < M)  store2(r0 + 8, c, acc[q][nt][2] + b0v, acc[q][nt][3] + b1v);
            }
        }
        __syncthreads();   // Bs reused next tile
    }
}

// ---------------- attention: warp per destination node, online softmax ----------------
__global__ void k_attn(int n) {
    int gw = (blockIdx.x * blockDim.x + threadIdx.x) >> 5;
    if (gw >= n) return;
    int lane = threadIdx.x & 31;
    int g = lane >> 3, l = lane & 7;
    int off = g * 32 + l * 4;
    const float scale = 0.17677669529663687f;  // 1/sqrt(32)

    float4 q = *(const float4*)(g_qs + (size_t)gw * QS_STRIDE + off);
    float m = -1e30f, ssum = 0.f;
    float ax = 0.f, ay = 0.f, az = 0.f, aw = 0.f;

    int beg = g_rowptr[gw], end = g_rowptr[gw + 1];

    float4 kc = make_float4(0, 0, 0, 0), vc = make_float4(0, 0, 0, 0);
    int sA = 0;
    if (beg < end) {
        int s0 = __ldg(g_esrc + beg);
        const float* kb = g_kv + (size_t)s0 * KV_STRIDE + off;
        kc = *(const float4*)kb;
        vc = *(const float4*)(kb + 128);
        if (beg + 1 < end) sA = __ldg(g_esrc + beg + 1);
    }

    for (int i = beg; i < end; ++i) {
        int sN = sA;
        if (i + 2 < end) sA = __ldg(g_esrc + i + 2);
        float4 kN = make_float4(0, 0, 0, 0), vN = kN;
        if (i + 1 < end) {
            const float* kb = g_kv + (size_t)sN * KV_STRIDE + off;
            kN = *(const float4*)kb;
            vN = *(const float4*)(kb + 128);
        }

        float d = q.x * kc.x + q.y * kc.y + q.z * kc.z + q.w * kc.w;
        d += __shfl_xor_sync(0xffffffffu, d, 1);
        d += __shfl_xor_sync(0xffffffffu, d, 2);
        d += __shfl_xor_sync(0xffffffffu, d, 4);
        float alpha = d * scale;
        if (alpha > m) {
            float sc = __expf(m - alpha);
            ssum = ssum * sc + 1.f;
            ax = ax * sc + vc.x;
            ay = ay * sc + vc.y;
            az = az * sc + vc.z;
            aw = aw * sc + vc.w;
            m = alpha;
        } else {
            float p = __expf(alpha - m);
            ssum += p;
            ax += p * vc.x;
            ay += p * vc.y;
            az += p * vc.z;
            aw += p * vc.w;
        }
        kc = kN; vc = vN;
    }
    float inv = (ssum > 0.f) ? (1.f / ssum) : 0.f;
    ax *= inv; ay *= inv; az *= inv; aw *= inv;

    ax += __shfl_xor_sync(0xffffffffu, ax, 8);
    ay += __shfl_xor_sync(0xffffffffu, ay, 8);
    az += __shfl_xor_sync(0xffffffffu, az, 8);
    aw += __shfl_xor_sync(0xffffffffu, aw, 8);
    ax += __shfl_xor_sync(0xffffffffu, ax, 16);
    ay += __shfl_xor_sync(0xffffffffu, ay, 16);
    az += __shfl_xor_sync(0xffffffffu, az, 16);
    aw += __shfl_xor_sync(0xffffffffu, aw, 16);

    if (lane < 8) {
        float4 sk = *(const float4*)(g_qs + (size_t)gw * QS_STRIDE + 128 + l * 4);
        float4 o;
        o.x = fmaxf(ax * 0.25f + sk.x, 0.f);
        o.y = fmaxf(ay * 0.25f + sk.y, 0.f);
        o.z = fmaxf(az * 0.25f + sk.z, 0.f);
        o.w = fmaxf(aw * 0.25f + sk.w, 0.f);
        *(float4*)(g_h + (size_t)gw * 32 + l * 4) = o;
    }
}

// ---------------- output projection: out[n,16] = h[n,32] @ Wout + bout ----------------
__global__ void __launch_bounds__(256) k_outproj(const float* __restrict__ Wout,
                                                 const float* __restrict__ bout,
                                                 float* __restrict__ out, int n) {
    __shared__ float Hs[128 * 32];
    __shared__ float Ws[512];
    __shared__ float Bs2[16];
    int node0 = blockIdx.x * 128;
    for (int i = threadIdx.x; i < 512; i += 256) Ws[i] = Wout[i];
    if (threadIdx.x < 16) Bs2[threadIdx.x] = bout[threadIdx.x];
    for (int i = threadIdx.x; i < 128 * 32; i += 256) {
        int r = node0 + (i >> 5);
        Hs[i] = (r < n) ? g_h[(size_t)node0 * 32 + i] : 0.f;
    }
    __syncthreads();
#pragma unroll
    for (int t = 0; t < 8; ++t) {
        int oi = threadIdx.x + t * 256;
        int ln = oi >> 4;
        int j = oi & 15;
        int node = node0 + ln;
        if (node >= n) continue;
        float acc = Bs2[j];
#pragma unroll
        for (int k = 0; k < 32; ++k) acc += Hs[ln * 32 + k] * Ws[k * 16 + j];
        out[(size_t)node * 16 + j] = acc;
    }
}

// ---------------- launch ----------------
extern "C" void kernel_launch(void* const* d_in, const int* in_sizes, int n_in,
                              void* d_out, int out_size) {
    const float* x = (const float*)d_in[0];
    const int*   ei = (const int*)d_in[1];
    int n = in_sizes[0] / 128;
    int e = in_sizes[1] / 2;
    const int* srcp = ei;
    const int* dstp = ei + e;

    const int smem0 = (448 + 128 * 132 + 128 * 136) * 4;   // K=128: ~136 KB
    const int smem1 = (448 + 128 * 36  + 32 * 136) * 4;    // K=32:  ~37 KB
    cudaFuncSetAttribute(k_gemm<128>, cudaFuncAttributeMaxDynamicSharedMemorySize, smem0);
    cudaFuncSetAttribute(k_gemm<32>,  cudaFuncAttributeMaxDynamicSharedMemorySize, smem1);

    int nb = (n + 255) / 256;
    int eb = (e + 255) / 256;
    int sblocks = (n + SCAN_B - 1) / SCAN_B;
    int gemm_blocks = (n + 127) / 128;
    int attn_blocks = (n + 7) / 8;
    int pack_total = 128 * NC + 32 * NC;

    // launch order keeps the L0 GEMM in the ncu capture slot (4th launch)
    k_pack_all<<<(pack_total + 255) / 256, 256>>>(
        (const float*)d_in[2],  (const float*)d_in[3],
        (const float*)d_in[4],  (const float*)d_in[5],
        (const float*)d_in[6],  (const float*)d_in[7],
        (const float*)d_in[8],  (const float*)d_in[9],
        (const float*)d_in[10], (const float*)d_in[11],
        (const float*)d_in[12], (const float*)d_in[13],
        (const float*)d_in[14], (const float*)d_in[15],
        (const float*)d_in[16], (const float*)d_in[17]);
    k_zero_cnt<<<nb, 256>>>(n);
    k_hist<<<eb, 256>>>(dstp, e);
    k_gemm<128><<<gemm_blocks, 256, smem0>>>(x, n);        // <- profiled slot
    k_scan1<<<sblocks, SCAN_B>>>(n);
    k_scan2<<<1, SCAN_B>>>(sblocks);
    k_scan3<<<sblocks, SCAN_B>>>(n);
    k_scatter<<<eb, 256>>>(srcp, dstp, e);
    k_attn<<<attn_blocks, 256>>>(n);
    k_gemm<32><<<gemm_blocks, 256, smem1>>>(nullptr, n);
    k_attn<<<attn_blocks, 256>>>(n);
    k_outproj<<<(n + 127) / 128, 256>>>(
        (const float*)d_in[18], (const float*)d_in[19], (float*)d_out, n);
}

// round 7
// speedup vs baseline: 1.2570x; 1.0414x over previous
#include <cuda_runtime.h>
#include <math.h>
#include <stdint.h>

// ---------------- problem constants ----------------
#define NMAX 100000
#define EMAX 800000
#define NC 416            // packed GEMM output cols: Q(128) K(128) V(128) S(32)
#define QS_STRIDE 160     // q(128) + skip(32)
#define KV_STRIDE 256     // k(128) + v(128)
#define SCAN_B 1024

// ---------------- scratch (device globals; no allocs allowed) ----------------
__device__ __align__(16) float g_qs[(size_t)NMAX * QS_STRIDE];
__device__ __align__(16) float g_kv[(size_t)NMAX * KV_STRIDE];
__device__ __align__(16) float g_h[(size_t)NMAX * 32];
__device__ __align__(16) float g_Wcat0[128 * NC];
__device__ __align__(16) float g_Wcat1[32 * NC];
__device__ float g_bcat0[NC];
__device__ float g_bcat1[NC];
__device__ int   g_cnt[NMAX];
__device__ int   g_rowptr[NMAX + 1];
__device__ int   g_cursor[NMAX];
__device__ int   g_esrc[EMAX];     // src node id per CSR slot (pre-gathered)
__device__ int   g_bsums[1024];

// ---------------- CSR build ----------------
__global__ void k_zero_cnt(int n) {
    int i = blockIdx.x * blockDim.x + threadIdx.x;
    if (i < n) g_cnt[i] = 0;
}

__global__ void k_hist(const int* __restrict__ dst, int e) {
    int i = blockIdx.x * blockDim.x + threadIdx.x;
    if (i < e) atomicAdd(&g_cnt[dst[i]], 1);
}

__global__ void k_scan1(int n) {
    __shared__ int sm[SCAN_B];
    int i = blockIdx.x * SCAN_B + threadIdx.x;
    int v = (i < n) ? g_cnt[i] : 0;
    sm[threadIdx.x] = v;
    for (int off = 1; off < SCAN_B; off <<= 1) {
        __syncthreads();
        int t = (threadIdx.x >= off) ? sm[threadIdx.x - off] : 0;
        __syncthreads();
        sm[threadIdx.x] += t;
    }
    __syncthreads();
    if (i < n) g_rowptr[i + 1] = sm[threadIdx.x];
    if (threadIdx.x == SCAN_B - 1) g_bsums[blockIdx.x] = sm[SCAN_B - 1];
}

__global__ void k_scan2(int nb) {
    __shared__ int sm[SCAN_B];
    int v = (threadIdx.x < nb) ? g_bsums[threadIdx.x] : 0;
    sm[threadIdx.x] = v;
    for (int off = 1; off < SCAN_B; off <<= 1) {
        __syncthreads();
        int t = (threadIdx.x >= off) ? sm[threadIdx.x - off] : 0;
        __syncthreads();
        sm[threadIdx.x] += t;
    }
    __syncthreads();
    if (threadIdx.x < nb) g_bsums[threadIdx.x] = sm[threadIdx.x] - v; // exclusive
}

// scan3 also derives cursor[i] = rowptr[i+1] - cnt[i], and rowptr[0]=0.
__global__ void k_scan3(int n) {
    int i = blockIdx.x * SCAN_B + threadIdx.x;
    if (i < n) {
        int v = g_rowptr[i + 1] + g_bsums[blockIdx.x];
        g_rowptr[i + 1] = v;
        g_cursor[i] = v - g_cnt[i];
    }
    if (i == 0) g_rowptr[0] = 0;
}

__global__ void k_scatter(const int* __restrict__ src, const int* __restrict__ dst, int e) {
    int i = blockIdx.x * blockDim.x + threadIdx.x;
    if (i < e) {
        int p = atomicAdd(&g_cursor[dst[i]], 1);
        g_esrc[p] = src[i];
    }
}

// ---------------- weight packing: Wcat[K][416] row-major + bias ----------------
__device__ __forceinline__ void pack_one(float* Wdst, float* bdst, int i, int K,
                                         const float* Wq, const float* bq,
                                         const float* Wk, const float* bk,
                                         const float* Wv, const float* bv,
                                         const float* Ws, const float* bs) {
    if (i < K * NC) {
        int k = i / NC, j = i % NC;
        float w;
        if (j < 128)      w = Wq[k * 128 + j];
        else if (j < 256) w = Wk[k * 128 + (j - 128)];
        else if (j < 384) w = Wv[k * 128 + (j - 256)];
        else              w = Ws[k * 32 + (j - 384)];
        Wdst[k * NC + j] = w;
    }
    if (i < NC) {
        float b;
        if (i < 128)      b = bq[i];
        else if (i < 256) b = bk[i - 128];
        else if (i < 384) b = bv[i - 256];
        else              b = bs[i - 384];
        bdst[i] = b;
    }
}

__global__ void k_pack_all(const float* Wq0, const float* bq0, const float* Wk0, const float* bk0,
                           const float* Wv0, const float* bv0, const float* Ws0, const float* bs0,
                           const float* Wq1, const float* bq1, const float* Wk1, const float* bk1,
                           const float* Wv1, const float* bv1, const float* Ws1, const float* bs1) {
    int i = blockIdx.x * blockDim.x + threadIdx.x;
    const int T0 = 128 * NC;
    if (i < T0)
        pack_one(g_Wcat0, g_bcat0, i, 128, Wq0, bq0, Wk0, bk0, Wv0, bv0, Ws0, bs0);
    else
        pack_one(g_Wcat1, g_bcat1, i - T0, 32, Wq1, bq1, Wk1, bk1, Wv1, bv1, Ws1, bs1);
}

// ---------------- TF32 tensor-core GEMM ----------------
// Block tile 128x128 (4 N-tiles over NC=416), 8 warps in 4x2 grid,
// warp tile 32x64 (A fragments reused across 8 n-subtiles).
// B loaded in K=64 chunks -> smem ~102 KB -> 2 CTAs/SM (16 warps) for
// latency hiding; __launch_bounds__(256,2) caps regs at 128.
__device__ __forceinline__ uint32_t f2tf32(float x) {
    uint32_t r;
    asm("cvt.rna.tf32.f32 %0, %1;" : "=r"(r) : "f"(x));
    return r;
}

__device__ __forceinline__ void mma_tf32(float c[4], uint32_t a0, uint32_t a1, uint32_t a2,
                                         uint32_t a3, uint32_t b0, uint32_t b1) {
    asm volatile(
        "mma.sync.aligned.m16n8k8.row.col.f32.tf32.tf32.f32 "
        "{%0,%1,%2,%3}, {%4,%5,%6,%7}, {%8,%9}, {%0,%1,%2,%3};\n"
        : "+f"(c[0]), "+f"(c[1]), "+f"(c[2]), "+f"(c[3])
        : "r"(a0), "r"(a1), "r"(a2), "r"(a3), "r"(b0), "r"(b1));
}

__device__ __forceinline__ void store2(int row, int c, float v0, float v1) {
    if (c < 128) {
        *(float2*)(g_qs + (size_t)row * QS_STRIDE + c) = make_float2(v0, v1);
    } else if (c < 384) {
        *(float2*)(g_kv + (size_t)row * KV_STRIDE + (c - 128)) = make_float2(v0, v1);
    } else {
        *(float2*)(g_qs + (size_t)row * QS_STRIDE + 128 + (c - 384)) = make_float2(v0, v1);
    }
}

template <int K>
__global__ void __launch_bounds__(256, 2) k_gemm(const float* __restrict__ A_ext, int M) {
    constexpr int KCH = (K < 64) ? K : 64;      // B chunk rows
    constexpr int NCHUNK = K / KCH;             // chunks per tile
    constexpr int AS = K + 4;                   // As row stride (mod32=4, conflict-free)
    constexpr int BS = 136;                     // Bs row stride (mod32=8, conflict-free)
    extern __shared__ float smf[];
    float* biassm = smf;                        // 448 floats
    float* As = smf + 448;                      // 128 x AS
    float* Bs = As + 128 * AS;                  // KCH x BS
    const bool Lyr1 = (K == 32);
    const float* __restrict__ A = Lyr1 ? g_h : A_ext;
    const float* __restrict__ Wc = Lyr1 ? g_Wcat1 : g_Wcat0;
    const float* __restrict__ bc = Lyr1 ? g_bcat1 : g_bcat0;

    int m0 = blockIdx.x * 128;
    int tid = threadIdx.x;
    int wid = tid >> 5, lane = tid & 31;
    int wm = wid >> 1, wn = wid & 1;            // 4 x 2 warp grid over 128x128
    int gid = lane >> 2, tig = lane & 3;

    for (int i = tid; i < NC; i += 256) biassm[i] = bc[i];

    // ---- load A once, tf32-converted ----
    constexpr int C4 = K / 4;
#pragma unroll
    for (int t = 0; t < (128 * C4) / 256; ++t) {
        int idx = tid + t * 256;
        int r = idx / C4;
        int c4 = idx % C4;
        float4 v = make_float4(0.f, 0.f, 0.f, 0.f);
        int gr = m0 + r;
        if (gr < M) v = *(const float4*)(A + (size_t)gr * K + c4 * 4);
        float4 o;
        o.x = __uint_as_float(f2tf32(v.x));
        o.y = __uint_as_float(f2tf32(v.y));
        o.z = __uint_as_float(f2tf32(v.z));
        o.w = __uint_as_float(f2tf32(v.w));
        *(float4*)&As[r * AS + c4 * 4] = o;
    }
    __syncthreads();

    // ---- N-tile loop: 4 tiles of 128 cols (last holds 32 real cols) ----
#pragma unroll 1
    for (int t4 = 0; t4 < 4; ++t4) {
        int n0 = t4 * 128;

        float acc[2][8][4];
#pragma unroll
        for (int q = 0; q < 2; ++q)
#pragma unroll
            for (int nt = 0; nt < 8; ++nt)
#pragma unroll
                for (int j = 0; j < 4; ++j) acc[q][nt][j] = 0.f;

#pragma unroll 1
        for (int ch = 0; ch < NCHUNK; ++ch) {
            int kbase = ch * KCH;
            // load B chunk [KCH][128] (tf32-converted)
#pragma unroll
            for (int u = 0; u < (KCH * 32) / 256; ++u) {
                int idx = tid + u * 256;
                int r = idx >> 5;               // k row within chunk
                int c4 = (idx & 31) << 2;       // col 0..124
                int gc = n0 + c4;
                float4 v = make_float4(0.f, 0.f, 0.f, 0.f);
                if (gc < NC) v = *(const float4*)(Wc + (size_t)(kbase + r) * NC + gc);
                float4 o;
                o.x = __uint_as_float(f2tf32(v.x));
                o.y = __uint_as_float(f2tf32(v.y));
                o.z = __uint_as_float(f2tf32(v.z));
                o.w = __uint_as_float(f2tf32(v.w));
                *(float4*)&Bs[r * BS + c4] = o;
            }
            __syncthreads();

#pragma unroll
            for (int kc = 0; kc < KCH / 8; ++kc) {
                int kkA = kbase + kc * 8;
                int kkB = kc * 8;
                uint32_t a[2][4];
#pragma unroll
                for (int q = 0; q < 2; ++q) {
                    int rb = wm * 32 + q * 16;
                    a[q][0] = __float_as_uint(As[(rb + gid) * AS + kkA + tig]);
                    a[q][1] = __float_as_uint(As[(rb + gid + 8) * AS + kkA + tig]);
                    a[q][2] = __float_as_uint(As[(rb + gid) * AS + kkA + tig + 4]);
                    a[q][3] = __float_as_uint(As[(rb + gid + 8) * AS + kkA + tig + 4]);
                }
                uint32_t b[8][2];
#pragma unroll
                for (int nt = 0; nt < 8; ++nt) {
                    int col = wn * 64 + nt * 8 + gid;
                    b[nt][0] = __float_as_uint(Bs[(kkB + tig) * BS + col]);
                    b[nt][1] = __float_as_uint(Bs[(kkB + tig + 4) * BS + col]);
                }
#pragma unroll
                for (int q = 0; q < 2; ++q)
#pragma unroll
                    for (int nt = 0; nt < 8; ++nt)
                        mma_tf32(acc[q][nt], a[q][0], a[q][1], a[q][2], a[q][3],
                                 b[nt][0], b[nt][1]);
            }
            __syncthreads();   // Bs reused next chunk/tile
        }

        // epilogue for this tile
#pragma unroll
        for (int q = 0; q < 2; ++q) {
            int r0 = m0 + wm * 32 + q * 16 + gid;
#pragma unroll
            for (int nt = 0; nt < 8; ++nt) {
                int c = n0 + wn * 64 + nt * 8 + tig * 2;
                if (c >= NC) continue;
                float b0v = biassm[c], b1v = biassm[c + 1];
                if (r0 < M)      store2(r0,     c, acc[q][nt][0] + b0v, acc[q][nt][1] + b1v);
                if (r0 + 8 < M)  store2(r0 + 8, c, acc[q][nt][2] + b0v, acc[q][nt][3] + b1v);
            }
        }
    }
}

// ---------------- attention: warp per destination node, online softmax ----------------
__global__ void k_attn(int n) {
    int gw = (blockIdx.x * blockDim.x + threadIdx.x) >> 5;
    if (gw >= n) return;
    int lane = threadIdx.x & 31;
    int g = lane >> 3, l = lane & 7;
    int off = g * 32 + l * 4;
    const float scale = 0.17677669529663687f;  // 1/sqrt(32)

    float4 q = *(const float4*)(g_qs + (size_t)gw * QS_STRIDE + off);
    float m = -1e30f, ssum = 0.f;
    float ax = 0.f, ay = 0.f, az = 0.f, aw = 0.f;

    int beg = g_rowptr[gw], end = g_rowptr[gw + 1];

    float4 kc = make_float4(0, 0, 0, 0), vc = make_float4(0, 0, 0, 0);
    int sA = 0;
    if (beg < end) {
        int s0 = __ldg(g_esrc + beg);
        const float* kb = g_kv + (size_t)s0 * KV_STRIDE + off;
        kc = *(const float4*)kb;
        vc = *(const float4*)(kb + 128);
        if (beg + 1 < end) sA = __ldg(g_esrc + beg + 1);
    }

    for (int i = beg; i < end; ++i) {
        int sN = sA;
        if (i + 2 < end) sA = __ldg(g_esrc + i + 2);
        float4 kN = make_float4(0, 0, 0, 0), vN = kN;
        if (i + 1 < end) {
            const float* kb = g_kv + (size_t)sN * KV_STRIDE + off;
            kN = *(const float4*)kb;
            vN = *(const float4*)(kb + 128);
        }

        float d = q.x * kc.x + q.y * kc.y + q.z * kc.z + q.w * kc.w;
        d += __shfl_xor_sync(0xffffffffu, d, 1);
        d += __shfl_xor_sync(0xffffffffu, d, 2);
        d += __shfl_xor_sync(0xffffffffu, d, 4);
        float alpha = d * scale;
        if (alpha > m) {
            float sc = __expf(m - alpha);
            ssum = ssum * sc + 1.f;
            ax = ax * sc + vc.x;
            ay = ay * sc + vc.y;
            az = az * sc + vc.z;
            aw = aw * sc + vc.w;
            m = alpha;
        } else {
            float p = __expf(alpha - m);
            ssum += p;
            ax += p * vc.x;
            ay += p * vc.y;
            az += p * vc.z;
            aw += p * vc.w;
        }
        kc = kN; vc = vN;
    }
    float inv = (ssum > 0.f) ? (1.f / ssum) : 0.f;
    ax *= inv; ay *= inv; az *= inv; aw *= inv;

    ax += __shfl_xor_sync(0xffffffffu, ax, 8);
    ay += __shfl_xor_sync(0xffffffffu, ay, 8);
    az += __shfl_xor_sync(0xffffffffu, az, 8);
    aw += __shfl_xor_sync(0xffffffffu, aw, 8);
    ax += __shfl_xor_sync(0xffffffffu, ax, 16);
    ay += __shfl_xor_sync(0xffffffffu, ay, 16);
    az += __shfl_xor_sync(0xffffffffu, az, 16);
    aw += __shfl_xor_sync(0xffffffffu, aw, 16);

    if (lane < 8) {
        float4 sk = *(const float4*)(g_qs + (size_t)gw * QS_STRIDE + 128 + l * 4);
        float4 o;
        o.x = fmaxf(ax * 0.25f + sk.x, 0.f);
        o.y = fmaxf(ay * 0.25f + sk.y, 0.f);
        o.z = fmaxf(az * 0.25f + sk.z, 0.f);
        o.w = fmaxf(aw * 0.25f + sk.w, 0.f);
        *(float4*)(g_h + (size_t)gw * 32 + l * 4) = o;
    }
}

// ---------------- output projection: out[n,16] = h[n,32] @ Wout + bout ----------------
__global__ void __launch_bounds__(256) k_outproj(const float* __restrict__ Wout,
                                                 const float* __restrict__ bout,
                                                 float* __restrict__ out, int n) {
    __shared__ float Hs[128 * 32];
    __shared__ float Ws[512];
    __shared__ float Bs2[16];
    int node0 = blockIdx.x * 128;
    for (int i = threadIdx.x; i < 512; i += 256) Ws[i] = Wout[i];
    if (threadIdx.x < 16) Bs2[threadIdx.x] = bout[threadIdx.x];
    for (int i = threadIdx.x; i < 128 * 32; i += 256) {
        int r = node0 + (i >> 5);
        Hs[i] = (r < n) ? g_h[(size_t)node0 * 32 + i] : 0.f;
    }
    __syncthreads();
#pragma unroll
    for (int t = 0; t < 8; ++t) {
        int oi = threadIdx.x + t * 256;
        int ln = oi >> 4;
        int j = oi & 15;
        int node = node0 + ln;
        if (node >= n) continue;
        float acc = Bs2[j];
#pragma unroll
        for (int k = 0; k < 32; ++k) acc += Hs[ln * 32 + k] * Ws[k * 16 + j];
        out[(size_t)node * 16 + j] = acc;
    }
}

// ---------------- launch ----------------
extern "C" void kernel_launch(void* const* d_in, const int* in_sizes, int n_in,
                              void* d_out, int out_size) {
    const float* x = (const float*)d_in[0];
    const int*   ei = (const int*)d_in[1];
    int n = in_sizes[0] / 128;
    int e = in_sizes[1] / 2;
    const int* srcp = ei;
    const int* dstp = ei + e;

    const int smem0 = (448 + 128 * 132 + 64 * 136) * 4;    // K=128: ~102 KB
    const int smem1 = (448 + 128 * 36  + 32 * 136) * 4;    // K=32:  ~37 KB
    cudaFuncSetAttribute(k_gemm<128>, cudaFuncAttributeMaxDynamicSharedMemorySize, smem0);
    cudaFuncSetAttribute(k_gemm<32>,  cudaFuncAttributeMaxDynamicSharedMemorySize, smem1);

    int nb = (n + 255) / 256;
    int eb = (e + 255) / 256;
    int sblocks = (n + SCAN_B - 1) / SCAN_B;
    int gemm_blocks = (n + 127) / 128;
    int attn_blocks = (n + 7) / 8;
    int pack_total = 128 * NC + 32 * NC;

    // launch order keeps the L0 GEMM in the ncu capture slot (4th launch)
    k_pack_all<<<(pack_total + 255) / 256, 256>>>(
        (const float*)d_in[2],  (const float*)d_in[3],
        (const float*)d_in[4],  (const float*)d_in[5],
        (const float*)d_in[6],  (const float*)d_in[7],
        (const float*)d_in[8],  (const float*)d_in[9],
        (const float*)d_in[10], (const float*)d_in[11],
        (const float*)d_in[12], (const float*)d_in[13],
        (const float*)d_in[14], (const float*)d_in[15],
        (const float*)d_in[16], (const float*)d_in[17]);
    k_zero_cnt<<<nb, 256>>>(n);
    k_hist<<<eb, 256>>>(dstp, e);
    k_gemm<128><<<gemm_blocks, 256, smem0>>>(x, n);        // <- profiled slot
    k_scan1<<<sblocks, SCAN_B>>>(n);
    k_scan2<<<1, SCAN_B>>>(sblocks);
    k_scan3<<<sblocks, SCAN_B>>>(n);
    k_scatter<<<eb, 256>>>(srcp, dstp, e);
    k_attn<<<attn_blocks, 256>>>(n);
    k_gemm<32><<<gemm_blocks, 256, smem1>>>(nullptr, n);
    k_attn<<<attn_blocks, 256>>>(n);
    k_outproj<<<(n + 127) / 128, 256>>>(
        (const float*)d_in[18], (const float*)d_in[19], (float*)d_out, n);
}

// round 8
// speedup vs baseline: 1.3430x; 1.0684x over previous
#include <cuda_runtime.h>
#include <math.h>
#include <stdint.h>

// ---------------- problem constants ----------------
#define NMAX 100000
#define EMAX 800000
#define NC 416            // packed GEMM output cols: Q(128) K(128) V(128) S(32)
#define QS_STRIDE 160     // q(128) + skip(32)
#define KV_STRIDE 256     // k(128) + v(128)
#define SCAN_B 1024

// ---------------- scratch (device globals; no allocs allowed) ----------------
__device__ __align__(16) float g_qs[(size_t)NMAX * QS_STRIDE];
__device__ __align__(16) float g_kv[(size_t)NMAX * KV_STRIDE];
__device__ __align__(16) float g_h[(size_t)NMAX * 32];
__device__ __align__(16) float g_Wcat0[128 * NC];
__device__ __align__(16) float g_Wcat1[32 * NC];
__device__ float g_bcat0[NC];
__device__ float g_bcat1[NC];
__device__ int   g_cnt[NMAX];
__device__ int   g_rowptr[NMAX + 1];
__device__ int   g_cursor[NMAX];
__device__ int   g_esrc[EMAX];     // src node id per CSR slot (pre-gathered)
__device__ int   g_bsums[1024];

// ---------------- CSR build ----------------
__global__ void k_zero_cnt(int n) {
    int i = blockIdx.x * blockDim.x + threadIdx.x;
    if (i < n) g_cnt[i] = 0;
}

__global__ void k_hist(const int* __restrict__ dst, int e) {
    int i = blockIdx.x * blockDim.x + threadIdx.x;
    if (i < e) atomicAdd(&g_cnt[dst[i]], 1);
}

__global__ void k_scan1(int n) {
    __shared__ int sm[SCAN_B];
    int i = blockIdx.x * SCAN_B + threadIdx.x;
    int v = (i < n) ? g_cnt[i] : 0;
    sm[threadIdx.x] = v;
    for (int off = 1; off < SCAN_B; off <<= 1) {
        __syncthreads();
        int t = (threadIdx.x >= off) ? sm[threadIdx.x - off] : 0;
        __syncthreads();
        sm[threadIdx.x] += t;
    }
    __syncthreads();
    if (i < n) g_rowptr[i + 1] = sm[threadIdx.x];
    if (threadIdx.x == SCAN_B - 1) g_bsums[blockIdx.x] = sm[SCAN_B - 1];
}

__global__ void k_scan2(int nb) {
    __shared__ int sm[SCAN_B];
    int v = (threadIdx.x < nb) ? g_bsums[threadIdx.x] : 0;
    sm[threadIdx.x] = v;
    for (int off = 1; off < SCAN_B; off <<= 1) {
        __syncthreads();
        int t = (threadIdx.x >= off) ? sm[threadIdx.x - off] : 0;
        __syncthreads();
        sm[threadIdx.x] += t;
    }
    __syncthreads();
    if (threadIdx.x < nb) g_bsums[threadIdx.x] = sm[threadIdx.x] - v; // exclusive
}

// scan3 also derives cursor[i] = rowptr[i+1] - cnt[i], and rowptr[0]=0.
__global__ void k_scan3(int n) {
    int i = blockIdx.x * SCAN_B + threadIdx.x;
    if (i < n) {
        int v = g_rowptr[i + 1] + g_bsums[blockIdx.x];
        g_rowptr[i + 1] = v;
        g_cursor[i] = v - g_cnt[i];
    }
    if (i == 0) g_rowptr[0] = 0;
}

__global__ void k_scatter(const int* __restrict__ src, const int* __restrict__ dst, int e) {
    int i = blockIdx.x * blockDim.x + threadIdx.x;
    if (i < e) {
        int p = atomicAdd(&g_cursor[dst[i]], 1);
        g_esrc[p] = src[i];
    }
}

// ---------------- weight packing: Wcat[K][416] row-major + bias ----------------
__device__ __forceinline__ void pack_one(float* Wdst, float* bdst, int i, int K,
                                         const float* Wq, const float* bq,
                                         const float* Wk, const float* bk,
                                         const float* Wv, const float* bv,
                                         const float* Ws, const float* bs) {
    if (i < K * NC) {
        int k = i / NC, j = i % NC;
        float w;
        if (j < 128)      w = Wq[k * 128 + j];
        else if (j < 256) w = Wk[k * 128 + (j - 128)];
        else if (j < 384) w = Wv[k * 128 + (j - 256)];
        else              w = Ws[k * 32 + (j - 384)];
        Wdst[k * NC + j] = w;
    }
    if (i < NC) {
        float b;
        if (i < 128)      b = bq[i];
        else if (i < 256) b = bk[i - 128];
        else if (i < 384) b = bv[i - 256];
        else              b = bs[i - 384];
        bdst[i] = b;
    }
}

__global__ void k_pack_all(const float* Wq0, const float* bq0, const float* Wk0, const float* bk0,
                           const float* Wv0, const float* bv0, const float* Ws0, const float* bs0,
                           const float* Wq1, const float* bq1, const float* Wk1, const float* bk1,
                           const float* Wv1, const float* bv1, const float* Ws1, const float* bs1) {
    int i = blockIdx.x * blockDim.x + threadIdx.x;
    const int T0 = 128 * NC;
    if (i < T0)
        pack_one(g_Wcat0, g_bcat0, i, 128, Wq0, bq0, Wk0, bk0, Wv0, bv0, Ws0, bs0);
    else
        pack_one(g_Wcat1, g_bcat1, i - T0, 32, Wq1, bq1, Wk1, bk1, Wv1, bv1, Ws1, bs1);
}

// ---------------- TF32 tensor-core GEMM (as round 7) ----------------
__device__ __forceinline__ uint32_t f2tf32(float x) {
    uint32_t r;
    asm("cvt.rna.tf32.f32 %0, %1;" : "=r"(r) : "f"(x));
    return r;
}

__device__ __forceinline__ void mma_tf32(float c[4], uint32_t a0, uint32_t a1, uint32_t a2,
                                         uint32_t a3, uint32_t b0, uint32_t b1) {
    asm volatile(
        "mma.sync.aligned.m16n8k8.row.col.f32.tf32.tf32.f32 "
        "{%0,%1,%2,%3}, {%4,%5,%6,%7}, {%8,%9}, {%0,%1,%2,%3};\n"
        : "+f"(c[0]), "+f"(c[1]), "+f"(c[2]), "+f"(c[3])
        : "r"(a0), "r"(a1), "r"(a2), "r"(a3), "r"(b0), "r"(b1));
}

__device__ __forceinline__ void store2(int row, int c, float v0, float v1) {
    if (c < 128) {
        *(float2*)(g_qs + (size_t)row * QS_STRIDE + c) = make_float2(v0, v1);
    } else if (c < 384) {
        *(float2*)(g_kv + (size_t)row * KV_STRIDE + (c - 128)) = make_float2(v0, v1);
    } else {
        *(float2*)(g_qs + (size_t)row * QS_STRIDE + 128 + (c - 384)) = make_float2(v0, v1);
    }
}

template <int K>
__global__ void __launch_bounds__(256, 2) k_gemm(const float* __restrict__ A_ext, int M) {
    constexpr int KCH = (K < 64) ? K : 64;      // B chunk rows
    constexpr int NCHUNK = K / KCH;             // chunks per tile
    constexpr int AS = K + 4;                   // As row stride (mod32=4, conflict-free)
    constexpr int BS = 136;                     // Bs row stride (mod32=8, conflict-free)
    extern __shared__ float smf[];
    float* biassm = smf;                        // 448 floats
    float* As = smf + 448;                      // 128 x AS
    float* Bs = As + 128 * AS;                  // KCH x BS
    const bool Lyr1 = (K == 32);
    const float* __restrict__ A = Lyr1 ? g_h : A_ext;
    const float* __restrict__ Wc = Lyr1 ? g_Wcat1 : g_Wcat0;
    const float* __restrict__ bc = Lyr1 ? g_bcat1 : g_bcat0;

    int m0 = blockIdx.x * 128;
    int tid = threadIdx.x;
    int wid = tid >> 5, lane = tid & 31;
    int wm = wid >> 1, wn = wid & 1;            // 4 x 2 warp grid over 128x128
    int gid = lane >> 2, tig = lane & 3;

    for (int i = tid; i < NC; i += 256) biassm[i] = bc[i];

    // ---- load A once, tf32-converted ----
    constexpr int C4 = K / 4;
#pragma unroll
    for (int t = 0; t < (128 * C4) / 256; ++t) {
        int idx = tid + t * 256;
        int r = idx / C4;
        int c4 = idx % C4;
        float4 v = make_float4(0.f, 0.f, 0.f, 0.f);
        int gr = m0 + r;
        if (gr < M) v = *(const float4*)(A + (size_t)gr * K + c4 * 4);
        float4 o;
        o.x = __uint_as_float(f2tf32(v.x));
        o.y = __uint_as_float(f2tf32(v.y));
        o.z = __uint_as_float(f2tf32(v.z));
        o.w = __uint_as_float(f2tf32(v.w));
        *(float4*)&As[r * AS + c4 * 4] = o;
    }
    __syncthreads();

    // ---- N-tile loop: 4 tiles of 128 cols (last holds 32 real cols) ----
#pragma unroll 1
    for (int t4 = 0; t4 < 4; ++t4) {
        int n0 = t4 * 128;

        float acc[2][8][4];
#pragma unroll
        for (int q = 0; q < 2; ++q)
#pragma unroll
            for (int nt = 0; nt < 8; ++nt)
#pragma unroll
                for (int j = 0; j < 4; ++j) acc[q][nt][j] = 0.f;

#pragma unroll 1
        for (int ch = 0; ch < NCHUNK; ++ch) {
            int kbase = ch * KCH;
#pragma unroll
            for (int u = 0; u < (KCH * 32) / 256; ++u) {
                int idx = tid + u * 256;
                int r = idx >> 5;
                int c4 = (idx & 31) << 2;
                int gc = n0 + c4;
                float4 v = make_float4(0.f, 0.f, 0.f, 0.f);
                if (gc < NC) v = *(const float4*)(Wc + (size_t)(kbase + r) * NC + gc);
                float4 o;
                o.x = __uint_as_float(f2tf32(v.x));
                o.y = __uint_as_float(f2tf32(v.y));
                o.z = __uint_as_float(f2tf32(v.z));
                o.w = __uint_as_float(f2tf32(v.w));
                *(float4*)&Bs[r * BS + c4] = o;
            }
            __syncthreads();

#pragma unroll
            for (int kc = 0; kc < KCH / 8; ++kc) {
                int kkA = kbase + kc * 8;
                int kkB = kc * 8;
                uint32_t a[2][4];
#pragma unroll
                for (int q = 0; q < 2; ++q) {
                    int rb = wm * 32 + q * 16;
                    a[q][0] = __float_as_uint(As[(rb + gid) * AS + kkA + tig]);
                    a[q][1] = __float_as_uint(As[(rb + gid + 8) * AS + kkA + tig]);
                    a[q][2] = __float_as_uint(As[(rb + gid) * AS + kkA + tig + 4]);
                    a[q][3] = __float_as_uint(As[(rb + gid + 8) * AS + kkA + tig + 4]);
                }
                uint32_t b[8][2];
#pragma unroll
                for (int nt = 0; nt < 8; ++nt) {
                    int col = wn * 64 + nt * 8 + gid;
                    b[nt][0] = __float_as_uint(Bs[(kkB + tig) * BS + col]);
                    b[nt][1] = __float_as_uint(Bs[(kkB + tig + 4) * BS + col]);
                }
#pragma unroll
                for (int q = 0; q < 2; ++q)
#pragma unroll
                    for (int nt = 0; nt < 8; ++nt)
                        mma_tf32(acc[q][nt], a[q][0], a[q][1], a[q][2], a[q][3],
                                 b[nt][0], b[nt][1]);
            }
            __syncthreads();
        }

        // epilogue for this tile
#pragma unroll
        for (int q = 0; q < 2; ++q) {
            int r0 = m0 + wm * 32 + q * 16 + gid;
#pragma unroll
            for (int nt = 0; nt < 8; ++nt) {
                int c = n0 + wn * 64 + nt * 8 + tig * 2;
                if (c >= NC) continue;
                float b0v = biassm[c], b1v = biassm[c + 1];
                if (r0 < M)      store2(r0,     c, acc[q][nt][0] + b0v, acc[q][nt][1] + b1v);
                if (r0 + 8 < M)  store2(r0 + 8, c, acc[q][nt][2] + b0v, acc[q][nt][3] + b1v);
            }
        }
    }
}

// ---------------- attention: warp/node online softmax, 2-edge unrolled ----------------
__device__ __forceinline__ float dotred8(float d) {
    d += __shfl_xor_sync(0xffffffffu, d, 1);
    d += __shfl_xor_sync(0xffffffffu, d, 2);
    d += __shfl_xor_sync(0xffffffffu, d, 4);
    return d;
}

__global__ void k_attn(int n) {
    int gw = (blockIdx.x * blockDim.x + threadIdx.x) >> 5;
    if (gw >= n) return;
    int lane = threadIdx.x & 31;
    int l = lane & 7;
    int off = (lane >> 3) * 32 + l * 4;
    const float scale = 0.17677669529663687f;  // 1/sqrt(32)

    float4 q = *(const float4*)(g_qs + (size_t)gw * QS_STRIDE + off);
    float m = -1e30f, ssum = 0.f;
    float ax = 0.f, ay = 0.f, az = 0.f, aw = 0.f;

    int beg = g_rowptr[gw], end = g_rowptr[gw + 1];
    int i = beg;

    // pairwise loop: 2 independent k/v load sets in flight, one rescale per pair
    for (; i + 1 < end; i += 2) {
        int s0 = __ldg(g_esrc + i);
        int s1 = __ldg(g_esrc + i + 1);
        const float* kb0 = g_kv + (size_t)s0 * KV_STRIDE + off;
        const float* kb1 = g_kv + (size_t)s1 * KV_STRIDE + off;
        float4 k0 = *(const float4*)kb0;
        float4 k1 = *(const float4*)kb1;
        float4 v0 = *(const float4*)(kb0 + 128);
        float4 v1 = *(const float4*)(kb1 + 128);

        float d0 = q.x * k0.x + q.y * k0.y + q.z * k0.z + q.w * k0.w;
        float d1 = q.x * k1.x + q.y * k1.y + q.z * k1.z + q.w * k1.w;
        d0 = dotred8(d0);
        d1 = dotred8(d1);
        float a0 = d0 * scale, a1 = d1 * scale;

        float mn = fmaxf(m, fmaxf(a0, a1));
        float sc = __expf(m - mn);          // 0 when m = -1e30
        float p0 = __expf(a0 - mn);
        float p1 = __expf(a1 - mn);
        ssum = ssum * sc + p0 + p1;
        ax = ax * sc + p0 * v0.x + p1 * v1.x;
        ay = ay * sc + p0 * v0.y + p1 * v1.y;
        az = az * sc + p0 * v0.z + p1 * v1.z;
        aw = aw * sc + p0 * v0.w + p1 * v1.w;
        m = mn;
    }
    if (i < end) {                           // tail edge
        int s0 = __ldg(g_esrc + i);
        const float* kb0 = g_kv + (size_t)s0 * KV_STRIDE + off;
        float4 k0 = *(const float4*)kb0;
        float4 v0 = *(const float4*)(kb0 + 128);
        float d0 = q.x * k0.x + q.y * k0.y + q.z * k0.z + q.w * k0.w;
        d0 = dotred8(d0);
        float a0 = d0 * scale;
        float mn = fmaxf(m, a0);
        float sc = __expf(m - mn);
        float p0 = __expf(a0 - mn);
        ssum = ssum * sc + p0;
        ax = ax * sc + p0 * v0.x;
        ay = ay * sc + p0 * v0.y;
        az = az * sc + p0 * v0.z;
        aw = aw * sc + p0 * v0.w;
        m = mn;
    }

    float inv = (ssum > 0.f) ? (1.f / ssum) : 0.f;
    ax *= inv; ay *= inv; az *= inv; aw *= inv;

    // mean over 4 heads
    ax += __shfl_xor_sync(0xffffffffu, ax, 8);
    ay += __shfl_xor_sync(0xffffffffu, ay, 8);
    az += __shfl_xor_sync(0xffffffffu, az, 8);
    aw += __shfl_xor_sync(0xffffffffu, aw, 8);
    ax += __shfl_xor_sync(0xffffffffu, ax, 16);
    ay += __shfl_xor_sync(0xffffffffu, ay, 16);
    az += __shfl_xor_sync(0xffffffffu, az, 16);
    aw += __shfl_xor_sync(0xffffffffu, aw, 16);

    if (lane < 8) {
        float4 sk = *(const float4*)(g_qs + (size_t)gw * QS_STRIDE + 128 + l * 4);
        float4 o;
        o.x = fmaxf(ax * 0.25f + sk.x, 0.f);
        o.y = fmaxf(ay * 0.25f + sk.y, 0.f);
        o.z = fmaxf(az * 0.25f + sk.z, 0.f);
        o.w = fmaxf(aw * 0.25f + sk.w, 0.f);
        *(float4*)(g_h + (size_t)gw * 32 + l * 4) = o;
    }
}

// ---------------- output projection: out[n,16] = h[n,32] @ Wout + bout ----------------
__global__ void __launch_bounds__(256) k_outproj(const float* __restrict__ Wout,
                                                 const float* __restrict__ bout,
                                                 float* __restrict__ out, int n) {
    __shared__ float Hs[128 * 32];
    __shared__ float Ws[512];
    __shared__ float Bs2[16];
    int node0 = blockIdx.x * 128;
    for (int i = threadIdx.x; i < 512; i += 256) Ws[i] = Wout[i];
    if (threadIdx.x < 16) Bs2[threadIdx.x] = bout[threadIdx.x];
    for (int i = threadIdx.x; i < 128 * 32; i += 256) {
        int r = node0 + (i >> 5);
        Hs[i] = (r < n) ? g_h[(size_t)node0 * 32 + i] : 0.f;
    }
    __syncthreads();
#pragma unroll
    for (int t = 0; t < 8; ++t) {
        int oi = threadIdx.x + t * 256;
        int ln = oi >> 4;
        int j = oi & 15;
        int node = node0 + ln;
        if (node >= n) continue;
        float acc = Bs2[j];
#pragma unroll
        for (int k = 0; k < 32; ++k) acc += Hs[ln * 32 + k] * Ws[k * 16 + j];
        out[(size_t)node * 16 + j] = acc;
    }
}

// ---------------- launch ----------------
static cudaStream_t g_s2 = nullptr;
static cudaEvent_t g_evF = nullptr, g_evJ = nullptr;

extern "C" void kernel_launch(void* const* d_in, const int* in_sizes, int n_in,
                              void* d_out, int out_size) {
    if (!g_s2) {
        cudaStreamCreateWithFlags(&g_s2, cudaStreamNonBlocking);
        cudaEventCreateWithFlags(&g_evF, cudaEventDisableTiming);
        cudaEventCreateWithFlags(&g_evJ, cudaEventDisableTiming);
    }
    const float* x = (const float*)d_in[0];
    const int*   ei = (const int*)d_in[1];
    int n = in_sizes[0] / 128;
    int e = in_sizes[1] / 2;
    const int* srcp = ei;
    const int* dstp = ei + e;

    const int smem0 = (448 + 128 * 132 + 64 * 136) * 4;    // K=128: ~102 KB
    const int smem1 = (448 + 128 * 36  + 32 * 136) * 4;    // K=32:  ~37 KB
    cudaFuncSetAttribute(k_gemm<128>, cudaFuncAttributeMaxDynamicSharedMemorySize, smem0);
    cudaFuncSetAttribute(k_gemm<32>,  cudaFuncAttributeMaxDynamicSharedMemorySize, smem1);

    int nb = (n + 255) / 256;
    int eb = (e + 255) / 256;
    int sblocks = (n + SCAN_B - 1) / SCAN_B;
    int gemm_blocks = (n + 127) / 128;
    int attn_blocks = (n + 7) / 8;
    int pack_total = 128 * NC + 32 * NC;

    // Fork: CSR build on side stream, overlapped with pack + layer-0 GEMM.
    cudaEventRecord(g_evF, 0);
    cudaStreamWaitEvent(g_s2, g_evF, 0);

    // main stream (launches 1,4 keep gemm<128> in the profiled slot)
    k_pack_all<<<(pack_total + 255) / 256, 256>>>(
        (const float*)d_in[2],  (const float*)d_in[3],
        (const float*)d_in[4],  (const float*)d_in[5],
        (const float*)d_in[6],  (const float*)d_in[7],
        (const float*)d_in[8],  (const float*)d_in[9],
        (const float*)d_in[10], (const float*)d_in[11],
        (const float*)d_in[12], (const float*)d_in[13],
        (const float*)d_in[14], (const float*)d_in[15],
        (const float*)d_in[16], (const float*)d_in[17]);
    k_zero_cnt<<<nb, 256, 0, g_s2>>>(n);
    k_hist<<<eb, 256, 0, g_s2>>>(dstp, e);
    k_gemm<128><<<gemm_blocks, 256, smem0>>>(x, n);        // <- profiled slot (4th)
    k_scan1<<<sblocks, SCAN_B, 0, g_s2>>>(n);
    k_scan2<<<1, SCAN_B, 0, g_s2>>>(sblocks);
    k_scan3<<<sblocks, SCAN_B, 0, g_s2>>>(n);
    k_scatter<<<eb, 256, 0, g_s2>>>(srcp, dstp, e);
    cudaEventRecord(g_evJ, g_s2);
    cudaStreamWaitEvent(0, g_evJ, 0);                      // join before attention

    k_attn<<<attn_blocks, 256>>>(n);
    k_gemm<32><<<gemm_blocks, 256, smem1>>>(nullptr, n);
    k_attn<<<attn_blocks, 256>>>(n);
    k_outproj<<<(n + 127) / 128, 256>>>(
        (const float*)d_in[18], (const float*)d_in[19], (float*)d_out, n);
}

// round 9
// speedup vs baseline: 1.5179x; 1.1302x over previous
#include <cuda_runtime.h>
#include <cuda_fp16.h>
#include <math.h>
#include <stdint.h>

// ---------------- problem constants ----------------
#define NMAX 100000
#define EMAX 800000
#define NC 416            // packed GEMM output cols: Q(128) K(128) V(128) S(32)
#define QS_STRIDE 160     // q(128) + skip(32), fp32
#define KV_STRIDE 256     // k(128) + v(128), fp16
#define SCAN_B 1024

// ---------------- scratch (device globals; no allocs allowed) ----------------
__device__ __align__(16) float  g_qs[(size_t)NMAX * QS_STRIDE];
__device__ __align__(16) __half g_kv[(size_t)NMAX * KV_STRIDE];   // fp16 k|v
__device__ __align__(16) float  g_h[(size_t)NMAX * 32];
__device__ __align__(16) float  g_Wcat0[128 * NC];
__device__ __align__(16) float  g_Wcat1[32 * NC];
__device__ float g_bcat0[NC];
__device__ float g_bcat1[NC];
__device__ int   g_cnt[NMAX];
__device__ int   g_rowptr[NMAX + 1];
__device__ int   g_cursor[NMAX];
__device__ int   g_esrc[EMAX];     // src node id per CSR slot (pre-gathered)
__device__ int   g_bsums[1024];

// ---------------- CSR build ----------------
__global__ void k_zero_cnt(int n) {
    int i = blockIdx.x * blockDim.x + threadIdx.x;
    if (i < n) g_cnt[i] = 0;
}

__global__ void k_hist(const int* __restrict__ dst, int e) {
    int i = blockIdx.x * blockDim.x + threadIdx.x;
    if (i < e) atomicAdd(&g_cnt[dst[i]], 1);
}

__global__ void k_scan1(int n) {
    __shared__ int sm[SCAN_B];
    int i = blockIdx.x * SCAN_B + threadIdx.x;
    int v = (i < n) ? g_cnt[i] : 0;
    sm[threadIdx.x] = v;
    for (int off = 1; off < SCAN_B; off <<= 1) {
        __syncthreads();
        int t = (threadIdx.x >= off) ? sm[threadIdx.x - off] : 0;
        __syncthreads();
        sm[threadIdx.x] += t;
    }
    __syncthreads();
    if (i < n) g_rowptr[i + 1] = sm[threadIdx.x];
    if (threadIdx.x == SCAN_B - 1) g_bsums[blockIdx.x] = sm[SCAN_B - 1];
}

__global__ void k_scan2(int nb) {
    __shared__ int sm[SCAN_B];
    int v = (threadIdx.x < nb) ? g_bsums[threadIdx.x] : 0;
    sm[threadIdx.x] = v;
    for (int off = 1; off < SCAN_B; off <<= 1) {
        __syncthreads();
        int t = (threadIdx.x >= off) ? sm[threadIdx.x - off] : 0;
        __syncthreads();
        sm[threadIdx.x] += t;
    }
    __syncthreads();
    if (threadIdx.x < nb) g_bsums[threadIdx.x] = sm[threadIdx.x] - v; // exclusive
}

// scan3 also derives cursor[i] = rowptr[i+1] - cnt[i], and rowptr[0]=0.
__global__ void k_scan3(int n) {
    int i = blockIdx.x * SCAN_B + threadIdx.x;
    if (i < n) {
        int v = g_rowptr[i + 1] + g_bsums[blockIdx.x];
        g_rowptr[i + 1] = v;
        g_cursor[i] = v - g_cnt[i];
    }
    if (i == 0) g_rowptr[0] = 0;
}

__global__ void k_scatter(const int* __restrict__ src, const int* __restrict__ dst, int e) {
    int i = blockIdx.x * blockDim.x + threadIdx.x;
    if (i < e) {
        int p = atomicAdd(&g_cursor[dst[i]], 1);
        g_esrc[p] = src[i];
    }
}

// ---------------- weight packing: Wcat[K][416] row-major + bias ----------------
__device__ __forceinline__ void pack_one(float* Wdst, float* bdst, int i, int K,
                                         const float* Wq, const float* bq,
                                         const float* Wk, const float* bk,
                                         const float* Wv, const float* bv,
                                         const float* Ws, const float* bs) {
    if (i < K * NC) {
        int k = i / NC, j = i % NC;
        float w;
        if (j < 128)      w = Wq[k * 128 + j];
        else if (j < 256) w = Wk[k * 128 + (j - 128)];
        else if (j < 384) w = Wv[k * 128 + (j - 256)];
        else              w = Ws[k * 32 + (j - 384)];
        Wdst[k * NC + j] = w;
    }
    if (i < NC) {
        float b;
        if (i < 128)      b = bq[i];
        else if (i < 256) b = bk[i - 128];
        else if (i < 384) b = bv[i - 256];
        else              b = bs[i - 384];
        bdst[i] = b;
    }
}

__global__ void k_pack_all(const float* Wq0, const float* bq0, const float* Wk0, const float* bk0,
                           const float* Wv0, const float* bv0, const float* Ws0, const float* bs0,
                           const float* Wq1, const float* bq1, const float* Wk1, const float* bk1,
                           const float* Wv1, const float* bv1, const float* Ws1, const float* bs1) {
    int i = blockIdx.x * blockDim.x + threadIdx.x;
    const int T0 = 128 * NC;
    if (i < T0)
        pack_one(g_Wcat0, g_bcat0, i, 128, Wq0, bq0, Wk0, bk0, Wv0, bv0, Ws0, bs0);
    else
        pack_one(g_Wcat1, g_bcat1, i - T0, 32, Wq1, bq1, Wk1, bk1, Wv1, bv1, Ws1, bs1);
}

// ---------------- TF32 tensor-core GEMM ----------------
__device__ __forceinline__ uint32_t f2tf32(float x) {
    uint32_t r;
    asm("cvt.rna.tf32.f32 %0, %1;" : "=r"(r) : "f"(x));
    return r;
}

__device__ __forceinline__ void mma_tf32(float c[4], uint32_t a0, uint32_t a1, uint32_t a2,
                                         uint32_t a3, uint32_t b0, uint32_t b1) {
    asm volatile(
        "mma.sync.aligned.m16n8k8.row.col.f32.tf32.tf32.f32 "
        "{%0,%1,%2,%3}, {%4,%5,%6,%7}, {%8,%9}, {%0,%1,%2,%3};\n"
        : "+f"(c[0]), "+f"(c[1]), "+f"(c[2]), "+f"(c[3])
        : "r"(a0), "r"(a1), "r"(a2), "r"(a3), "r"(b0), "r"(b1));
}

// route GEMM output: q/skip stay fp32 in g_qs; k/v go fp16 into g_kv
__device__ __forceinline__ void store2(int row, int c, float v0, float v1) {
    if (c < 128) {
        *(float2*)(g_qs + (size_t)row * QS_STRIDE + c) = make_float2(v0, v1);
    } else if (c < 384) {
        *(__half2*)(g_kv + (size_t)row * KV_STRIDE + (c - 128)) = __floats2half2_rn(v0, v1);
    } else {
        *(float2*)(g_qs + (size_t)row * QS_STRIDE + 128 + (c - 384)) = make_float2(v0, v1);
    }
}

template <int K>
__global__ void __launch_bounds__(256, 2) k_gemm(const float* __restrict__ A_ext, int M) {
    constexpr int KCH = (K < 64) ? K : 64;      // B chunk rows
    constexpr int NCHUNK = K / KCH;             // chunks per tile
    constexpr int AS = K + 4;                   // As row stride (mod32=4, conflict-free)
    constexpr int BS = 136;                     // Bs row stride (mod32=8, conflict-free)
    extern __shared__ float smf[];
    float* biassm = smf;                        // 448 floats
    float* As = smf + 448;                      // 128 x AS
    float* Bs = As + 128 * AS;                  // KCH x BS
    const bool Lyr1 = (K == 32);
    const float* __restrict__ A = Lyr1 ? g_h : A_ext;
    const float* __restrict__ Wc = Lyr1 ? g_Wcat1 : g_Wcat0;
    const float* __restrict__ bc = Lyr1 ? g_bcat1 : g_bcat0;

    int m0 = blockIdx.x * 128;
    int tid = threadIdx.x;
    int wid = tid >> 5, lane = tid & 31;
    int wm = wid >> 1, wn = wid & 1;            // 4 x 2 warp grid over 128x128
    int gid = lane >> 2, tig = lane & 3;

    for (int i = tid; i < NC; i += 256) biassm[i] = bc[i];

    // ---- load A once, tf32-converted ----
    constexpr int C4 = K / 4;
#pragma unroll
    for (int t = 0; t < (128 * C4) / 256; ++t) {
        int idx = tid + t * 256;
        int r = idx / C4;
        int c4 = idx % C4;
        float4 v = make_float4(0.f, 0.f, 0.f, 0.f);
        int gr = m0 + r;
        if (gr < M) v = *(const float4*)(A + (size_t)gr * K + c4 * 4);
        float4 o;
        o.x = __uint_as_float(f2tf32(v.x));
        o.y = __uint_as_float(f2tf32(v.y));
        o.z = __uint_as_float(f2tf32(v.z));
        o.w = __uint_as_float(f2tf32(v.w));
        *(float4*)&As[r * AS + c4 * 4] = o;
    }
    __syncthreads();

    // ---- N-tile loop: 4 tiles of 128 cols (last holds 32 real cols) ----
#pragma unroll 1
    for (int t4 = 0; t4 < 4; ++t4) {
        int n0 = t4 * 128;

        float acc[2][8][4];
#pragma unroll
        for (int q = 0; q < 2; ++q)
#pragma unroll
            for (int nt = 0; nt < 8; ++nt)
#pragma unroll
                for (int j = 0; j < 4; ++j) acc[q][nt][j] = 0.f;

#pragma unroll 1
        for (int ch = 0; ch < NCHUNK; ++ch) {
            int kbase = ch * KCH;
#pragma unroll
            for (int u = 0; u < (KCH * 32) / 256; ++u) {
                int idx = tid + u * 256;
                int r = idx >> 5;
                int c4 = (idx & 31) << 2;
                int gc = n0 + c4;
                float4 v = make_float4(0.f, 0.f, 0.f, 0.f);
                if (gc < NC) v = *(const float4*)(Wc + (size_t)(kbase + r) * NC + gc);
                float4 o;
                o.x = __uint_as_float(f2tf32(v.x));
                o.y = __uint_as_float(f2tf32(v.y));
                o.z = __uint_as_float(f2tf32(v.z));
                o.w = __uint_as_float(f2tf32(v.w));
                *(float4*)&Bs[r * BS + c4] = o;
            }
            __syncthreads();

#pragma unroll
            for (int kc = 0; kc < KCH / 8; ++kc) {
                int kkA = kbase + kc * 8;
                int kkB = kc * 8;
                uint32_t a[2][4];
#pragma unroll
                for (int q = 0; q < 2; ++q) {
                    int rb = wm * 32 + q * 16;
                    a[q][0] = __float_as_uint(As[(rb + gid) * AS + kkA + tig]);
                    a[q][1] = __float_as_uint(As[(rb + gid + 8) * AS + kkA + tig]);
                    a[q][2] = __float_as_uint(As[(rb + gid) * AS + kkA + tig + 4]);
                    a[q][3] = __float_as_uint(As[(rb + gid + 8) * AS + kkA + tig + 4]);
                }
                uint32_t b[8][2];
#pragma unroll
                for (int nt = 0; nt < 8; ++nt) {
                    int col = wn * 64 + nt * 8 + gid;
                    b[nt][0] = __float_as_uint(Bs[(kkB + tig) * BS + col]);
                    b[nt][1] = __float_as_uint(Bs[(kkB + tig + 4) * BS + col]);
                }
#pragma unroll
                for (int q = 0; q < 2; ++q)
#pragma unroll
                    for (int nt = 0; nt < 8; ++nt)
                        mma_tf32(acc[q][nt], a[q][0], a[q][1], a[q][2], a[q][3],
                                 b[nt][0], b[nt][1]);
            }
            __syncthreads();
        }

        // epilogue for this tile
#pragma unroll
        for (int q = 0; q < 2; ++q) {
            int r0 = m0 + wm * 32 + q * 16 + gid;
#pragma unroll
            for (int nt = 0; nt < 8; ++nt) {
                int c = n0 + wn * 64 + nt * 8 + tig * 2;
                if (c >= NC) continue;
                float b0v = biassm[c], b1v = biassm[c + 1];
                if (r0 < M)      store2(r0,     c, acc[q][nt][0] + b0v, acc[q][nt][1] + b1v);
                if (r0 + 8 < M)  store2(r0 + 8, c, acc[q][nt][2] + b0v, acc[q][nt][3] + b1v);
            }
        }
    }
}

// ---------------- attention: warp/node online softmax, 4-edge batches, fp16 kv ----------------
__device__ __forceinline__ float4 h4_to_f4(uint2 u) {
    __half2 h0 = *reinterpret_cast<__half2*>(&u.x);
    __half2 h1 = *reinterpret_cast<__half2*>(&u.y);
    float2 f0 = __half22float2(h0);
    float2 f1 = __half22float2(h1);
    return make_float4(f0.x, f0.y, f1.x, f1.y);
}

__global__ void k_attn(int n) {
    int gw = (blockIdx.x * blockDim.x + threadIdx.x) >> 5;
    if (gw >= n) return;
    int lane = threadIdx.x & 31;
    int l = lane & 7;
    int off = (lane >> 3) * 32 + l * 4;
    const float scale = 0.17677669529663687f;  // 1/sqrt(32)

    float4 q = *(const float4*)(g_qs + (size_t)gw * QS_STRIDE + off);
    float m = -1e30f, ssum = 0.f;
    float ax = 0.f, ay = 0.f, az = 0.f, aw = 0.f;

    int beg = g_rowptr[gw], end = g_rowptr[gw + 1];

    for (int base = beg; base < end; base += 4) {
        int cnt = end - base; if (cnt > 4) cnt = 4;
        int s[4];
#pragma unroll
        for (int j = 0; j < 4; ++j)
            s[j] = __ldg(g_esrc + base + ((j < cnt) ? j : 0));

        // all k/v loads independent (fp16, 8B each)
        float4 kk[4], vv[4];
#pragma unroll
        for (int j = 0; j < 4; ++j) {
            const __half* kb = g_kv + (size_t)s[j] * KV_STRIDE + off;
            uint2 ku = *(const uint2*)kb;
            uint2 vu = *(const uint2*)(kb + 128);
            kk[j] = h4_to_f4(ku);
            vv[j] = h4_to_f4(vu);
        }

        float d[4];
#pragma unroll
        for (int j = 0; j < 4; ++j)
            d[j] = q.x * kk[j].x + q.y * kk[j].y + q.z * kk[j].z + q.w * kk[j].w;
        // interleaved shuffle reductions (independent chains)
#pragma unroll
        for (int st = 1; st <= 4; st <<= 1)
#pragma unroll
            for (int j = 0; j < 4; ++j)
                d[j] += __shfl_xor_sync(0xffffffffu, d[j], st);

        float a[4];
#pragma unroll
        for (int j = 0; j < 4; ++j)
            a[j] = (j < cnt) ? d[j] * scale : -1e30f;

        float bm = fmaxf(fmaxf(a[0], a[1]), fmaxf(a[2], a[3]));
        float mn = fmaxf(m, bm);
        float sc = __expf(m - mn);          // 0 on first batch
        float p[4];
#pragma unroll
        for (int j = 0; j < 4; ++j) p[j] = __expf(a[j] - mn);

        ssum = ssum * sc + p[0] + p[1] + p[2] + p[3];
        ax = ax * sc + p[0] * vv[0].x + p[1] * vv[1].x + p[2] * vv[2].x + p[3] * vv[3].x;
        ay = ay * sc + p[0] * vv[0].y + p[1] * vv[1].y + p[2] * vv[2].y + p[3] * vv[3].y;
        az = az * sc + p[0] * vv[0].z + p[1] * vv[1].z + p[2] * vv[2].z + p[3] * vv[3].z;
        aw = aw * sc + p[0] * vv[0].w + p[1] * vv[1].w + p[2] * vv[2].w + p[3] * vv[3].w;
        m = mn;
    }

    float inv = (ssum > 0.f) ? (1.f / ssum) : 0.f;
    ax *= inv; ay *= inv; az *= inv; aw *= inv;

    // mean over 4 heads
    ax += __shfl_xor_sync(0xffffffffu, ax, 8);
    ay += __shfl_xor_sync(0xffffffffu, ay, 8);
    az += __shfl_xor_sync(0xffffffffu, az, 8);
    aw += __shfl_xor_sync(0xffffffffu, aw, 8);
    ax += __shfl_xor_sync(0xffffffffu, ax, 16);
    ay += __shfl_xor_sync(0xffffffffu, ay, 16);
    az += __shfl_xor_sync(0xffffffffu, az, 16);
    aw += __shfl_xor_sync(0xffffffffu, aw, 16);

    if (lane < 8) {
        float4 sk = *(const float4*)(g_qs + (size_t)gw * QS_STRIDE + 128 + l * 4);
        float4 o;
        o.x = fmaxf(ax * 0.25f + sk.x, 0.f);
        o.y = fmaxf(ay * 0.25f + sk.y, 0.f);
        o.z = fmaxf(az * 0.25f + sk.z, 0.f);
        o.w = fmaxf(aw * 0.25f + sk.w, 0.f);
        *(float4*)(g_h + (size_t)gw * 32 + l * 4) = o;
    }
}

// ---------------- output projection: out[n,16] = h[n,32] @ Wout + bout ----------------
__global__ void __launch_bounds__(256) k_outproj(const float* __restrict__ Wout,
                                                 const float* __restrict__ bout,
                                                 float* __restrict__ out, int n) {
    __shared__ float Hs[128 * 32];
    __shared__ float Ws[512];
    __shared__ float Bs2[16];
    int node0 = blockIdx.x * 128;
    for (int i = threadIdx.x; i < 512; i += 256) Ws[i] = Wout[i];
    if (threadIdx.x < 16) Bs2[threadIdx.x] = bout[threadIdx.x];
    for (int i = threadIdx.x; i < 128 * 32; i += 256) {
        int r = node0 + (i >> 5);
        Hs[i] = (r < n) ? g_h[(size_t)node0 * 32 + i] : 0.f;
    }
    __syncthreads();
#pragma unroll
    for (int t = 0; t < 8; ++t) {
        int oi = threadIdx.x + t * 256;
        int ln = oi >> 4;
        int j = oi & 15;
        int node = node0 + ln;
        if (node >= n) continue;
        float acc = Bs2[j];
#pragma unroll
        for (int k = 0; k < 32; ++k) acc += Hs[ln * 32 + k] * Ws[k * 16 + j];
        out[(size_t)node * 16 + j] = acc;
    }
}

// ---------------- launch ----------------
static cudaStream_t g_s2 = nullptr;
static cudaEvent_t g_evF = nullptr, g_evJ = nullptr;

extern "C" void kernel_launch(void* const* d_in, const int* in_sizes, int n_in,
                              void* d_out, int out_size) {
    if (!g_s2) {
        cudaStreamCreateWithFlags(&g_s2, cudaStreamNonBlocking);
        cudaEventCreateWithFlags(&g_evF, cudaEventDisableTiming);
        cudaEventCreateWithFlags(&g_evJ, cudaEventDisableTiming);
    }
    const float* x = (const float*)d_in[0];
    const int*   ei = (const int*)d_in[1];
    int n = in_sizes[0] / 128;
    int e = in_sizes[1] / 2;
    const int* srcp = ei;
    const int* dstp = ei + e;

    const int smem0 = (448 + 128 * 132 + 64 * 136) * 4;    // K=128: ~102 KB
    const int smem1 = (448 + 128 * 36  + 32 * 136) * 4;    // K=32:  ~37 KB
    cudaFuncSetAttribute(k_gemm<128>, cudaFuncAttributeMaxDynamicSharedMemorySize, smem0);
    cudaFuncSetAttribute(k_gemm<32>,  cudaFuncAttributeMaxDynamicSharedMemorySize, smem1);

    int nb = (n + 255) / 256;
    int eb = (e + 255) / 256;
    int sblocks = (n + SCAN_B - 1) / SCAN_B;
    int gemm_blocks = (n + 127) / 128;
    int attn_blocks = (n + 7) / 8;
    int pack_total = 128 * NC + 32 * NC;

    // Fork: CSR build on side stream, overlapped with pack + layer-0 GEMM.
    cudaEventRecord(g_evF, 0);
    cudaStreamWaitEvent(g_s2, g_evF, 0);

    // main stream (submissions 1,4 keep gemm<128> in the profiled slot)
    k_pack_all<<<(pack_total + 255) / 256, 256>>>(
        (const float*)d_in[2],  (const float*)d_in[3],
        (const float*)d_in[4],  (const float*)d_in[5],
        (const float*)d_in[6],  (const float*)d_in[7],
        (const float*)d_in[8],  (const float*)d_in[9],
        (const float*)d_in[10], (const float*)d_in[11],
        (const float*)d_in[12], (const float*)d_in[13],
        (const float*)d_in[14], (const float*)d_in[15],
        (const float*)d_in[16], (const float*)d_in[17]);
    k_zero_cnt<<<nb, 256, 0, g_s2>>>(n);
    k_hist<<<eb, 256, 0, g_s2>>>(dstp, e);
    k_gemm<128><<<gemm_blocks, 256, smem0>>>(x, n);        // <- profiled slot (4th)
    k_scan1<<<sblocks, SCAN_B, 0, g_s2>>>(n);
    k_scan2<<<1, SCAN_B, 0, g_s2>>>(sblocks);
    k_scan3<<<sblocks, SCAN_B, 0, g_s2>>>(n);
    k_scatter<<<eb, 256, 0, g_s2>>>(srcp, dstp, e);
    cudaEventRecord(g_evJ, g_s2);
    cudaStreamWaitEvent(0, g_evJ, 0);                      // join before attention

    k_attn<<<attn_blocks, 256>>>(n);
    k_gemm<32><<<gemm_blocks, 256, smem1>>>(nullptr, n);
    k_attn<<<attn_blocks, 256>>>(n);
    k_outproj<<<(n + 127) / 128, 256>>>(
        (const float*)d_in[18], (const float*)d_in[19], (float*)d_out, n);
}

// round 10
// speedup vs baseline: 1.7567x; 1.1573x over previous
#include <cuda_runtime.h>
#include <cuda_fp16.h>
#include <math.h>
#include <stdint.h>

// ---------------- problem constants ----------------
#define NMAX 100000
#define EMAX 800000
#define NC 416            // packed GEMM output cols: Q(128) K(128) V(128) S(32)
#define QS_STRIDE 160     // q(128) + skip(32), fp32
#define KV_STRIDE 256     // k(128) + v(128), fp16
#define SCAN_B 1024

// ---------------- scratch (device globals; no allocs allowed) ----------------
__device__ __align__(16) float  g_qs[(size_t)NMAX * QS_STRIDE];
__device__ __align__(16) __half g_kv[(size_t)NMAX * KV_STRIDE];   // fp16 k|v
__device__ __align__(16) float  g_h[(size_t)NMAX * 32];
__device__ __align__(16) __half g_Wt0[NC * 128];   // layer0 weights, fp16, [n][k]
__device__ __align__(16) __half g_Wt1[NC * 32];    // layer1 weights, fp16, [n][k]
__device__ float g_bcat0[NC];
__device__ float g_bcat1[NC];
__device__ int   g_cnt[NMAX];
__device__ int   g_rowptr[NMAX + 1];
__device__ int   g_cursor[NMAX];
__device__ int   g_esrc[EMAX];     // src node id per CSR slot (pre-gathered)
__device__ int   g_bsums[1024];

// ---------------- CSR build ----------------
__global__ void k_zero_cnt(int n) {
    int i = blockIdx.x * blockDim.x + threadIdx.x;
    if (i < n) g_cnt[i] = 0;
}

__global__ void k_hist(const int* __restrict__ dst, int e) {
    int i = blockIdx.x * blockDim.x + threadIdx.x;
    if (i < e) atomicAdd(&g_cnt[dst[i]], 1);
}

__global__ void k_scan1(int n) {
    __shared__ int sm[SCAN_B];
    int i = blockIdx.x * SCAN_B + threadIdx.x;
    int v = (i < n) ? g_cnt[i] : 0;
    sm[threadIdx.x] = v;
    for (int off = 1; off < SCAN_B; off <<= 1) {
        __syncthreads();
        int t = (threadIdx.x >= off) ? sm[threadIdx.x - off] : 0;
        __syncthreads();
        sm[threadIdx.x] += t;
    }
    __syncthreads();
    if (i < n) g_rowptr[i + 1] = sm[threadIdx.x];
    if (threadIdx.x == SCAN_B - 1) g_bsums[blockIdx.x] = sm[SCAN_B - 1];
}

__global__ void k_scan2(int nb) {
    __shared__ int sm[SCAN_B];
    int v = (threadIdx.x < nb) ? g_bsums[threadIdx.x] : 0;
    sm[threadIdx.x] = v;
    for (int off = 1; off < SCAN_B; off <<= 1) {
        __syncthreads();
        int t = (threadIdx.x >= off) ? sm[threadIdx.x - off] : 0;
        __syncthreads();
        sm[threadIdx.x] += t;
    }
    __syncthreads();
    if (threadIdx.x < nb) g_bsums[threadIdx.x] = sm[threadIdx.x] - v; // exclusive
}

// scan3 also derives cursor[i] = rowptr[i+1] - cnt[i], and rowptr[0]=0.
__global__ void k_scan3(int n) {
    int i = blockIdx.x * SCAN_B + threadIdx.x;
    if (i < n) {
        int v = g_rowptr[i + 1] + g_bsums[blockIdx.x];
        g_rowptr[i + 1] = v;
        g_cursor[i] = v - g_cnt[i];
    }
    if (i == 0) g_rowptr[0] = 0;
}

__global__ void k_scatter(const int* __restrict__ src, const int* __restrict__ dst, int e) {
    int i = blockIdx.x * blockDim.x + threadIdx.x;
    if (i < e) {
        int p = atomicAdd(&g_cursor[dst[i]], 1);
        g_esrc[p] = src[i];
    }
}

// ---------------- weight packing: fp16 transposed [n][K] + fp32 bias ----------------
__global__ void k_pack_all(const float* Wq0, const float* bq0, const float* Wk0, const float* bk0,
                           const float* Wv0, const float* bv0, const float* Ws0, const float* bs0,
                           const float* Wq1, const float* bq1, const float* Wk1, const float* bk1,
                           const float* Wv1, const float* bv1, const float* Ws1, const float* bs1) {
    int i = blockIdx.x * blockDim.x + threadIdx.x;
    const int T0 = NC * 128;
    const int T1 = NC * 32;
    if (i < T0) {
        int n = i >> 7, k = i & 127;
        float w = (n < 128) ? Wq0[k * 128 + n]
                : (n < 256) ? Wk0[k * 128 + (n - 128)]
                : (n < 384) ? Wv0[k * 128 + (n - 256)]
                            : Ws0[k * 32 + (n - 384)];
        g_Wt0[i] = __float2half_rn(w);
    } else if (i < T0 + T1) {
        int j = i - T0;
        int n = j >> 5, k = j & 31;
        float w = (n < 128) ? Wq1[k * 128 + n]
                : (n < 256) ? Wk1[k * 128 + (n - 128)]
                : (n < 384) ? Wv1[k * 128 + (n - 256)]
                            : Ws1[k * 32 + (n - 384)];
        g_Wt1[j] = __float2half_rn(w);
    } else if (i < T0 + T1 + NC) {
        int c = i - T0 - T1;
        g_bcat0[c] = (c < 128) ? bq0[c] : (c < 256) ? bk0[c - 128]
                   : (c < 384) ? bv0[c - 256] : bs0[c - 384];
    } else if (i < T0 + T1 + 2 * NC) {
        int c = i - T0 - T1 - NC;
        g_bcat1[c] = (c < 128) ? bq1[c] : (c < 256) ? bk1[c - 128]
                   : (c < 384) ? bv1[c - 256] : bs1[c - 384];
    }
}

// ---------------- FP16 tensor-core GEMM (m16n8k16, fp32 accumulate) ----------------
// Block tile 128x128 (4 N-tiles over NC=416), 8 warps 4x2, warp tile 32x64.
// As [128 rows][K] fp16 stride K+8; Bs [128 n][K] fp16 stride K+8 (B transposed
// in global). All fragment loads 4B, conflict-free (stride bytes ≡ 16 mod 128).
__device__ __forceinline__ void mma_f16(float c[4], uint32_t a0, uint32_t a1, uint32_t a2,
                                        uint32_t a3, uint32_t b0, uint32_t b1) {
    asm volatile(
        "mma.sync.aligned.m16n8k16.row.col.f32.f16.f16.f32 "
        "{%0,%1,%2,%3}, {%4,%5,%6,%7}, {%8,%9}, {%0,%1,%2,%3};\n"
        : "+f"(c[0]), "+f"(c[1]), "+f"(c[2]), "+f"(c[3])
        : "r"(a0), "r"(a1), "r"(a2), "r"(a3), "r"(b0), "r"(b1));
}

// route GEMM output: q/skip stay fp32 in g_qs; k/v go fp16 into g_kv
__device__ __forceinline__ void store2(int row, int c, float v0, float v1) {
    if (c < 128) {
        *(float2*)(g_qs + (size_t)row * QS_STRIDE + c) = make_float2(v0, v1);
    } else if (c < 384) {
        *(__half2*)(g_kv + (size_t)row * KV_STRIDE + (c - 128)) = __floats2half2_rn(v0, v1);
    } else {
        *(float2*)(g_qs + (size_t)row * QS_STRIDE + 128 + (c - 384)) = make_float2(v0, v1);
    }
}

template <int K>
__global__ void __launch_bounds__(256, 2) k_gemm(const float* __restrict__ A_ext, int M) {
    constexpr int ST = K + 8;                   // fp16 stride (byte stride ≡ 16 mod 128)
    extern __shared__ char smem[];
    float* biassm = (float*)smem;               // 448 floats
    __half* As = (__half*)(smem + 1792);        // 128 x ST
    __half* Bs = As + 128 * ST;                 // 128 x ST
    const bool Lyr1 = (K == 32);
    const float* __restrict__ A = Lyr1 ? g_h : A_ext;
    const __half* __restrict__ Wt = Lyr1 ? g_Wt1 : g_Wt0;
    const float* __restrict__ bc = Lyr1 ? g_bcat1 : g_bcat0;

    int m0 = blockIdx.x * 128;
    int tid = threadIdx.x;
    int wid = tid >> 5, lane = tid & 31;
    int wm = wid >> 1, wn = wid & 1;            // 4 x 2 warp grid over 128x128
    int gid = lane >> 2, tig = lane & 3;

    for (int i = tid; i < NC; i += 256) biassm[i] = bc[i];

    // ---- load A once, fp16-converted ----
    constexpr int C4 = K / 4;
#pragma unroll
    for (int t = 0; t < (128 * C4) / 256; ++t) {
        int idx = tid + t * 256;
        int r = idx / C4;
        int c4 = idx % C4;
        float4 v = make_float4(0.f, 0.f, 0.f, 0.f);
        int gr = m0 + r;
        if (gr < M) v = *(const float4*)(A + (size_t)gr * K + c4 * 4);
        __half2 h0 = __floats2half2_rn(v.x, v.y);
        __half2 h1 = __floats2half2_rn(v.z, v.w);
        uint2 pk = make_uint2(*(uint32_t*)&h0, *(uint32_t*)&h1);
        *(uint2*)&As[r * ST + c4 * 4] = pk;
    }
    __syncthreads();

    // ---- N-tile loop: 4 tiles of 128 cols (last holds 32 real cols) ----
#pragma unroll 1
    for (int t4 = 0; t4 < 4; ++t4) {
        int n0 = t4 * 128;

        // load B tile: 128 transposed rows (global cols), K fp16 each, 16B chunks
        constexpr int CH = K / 8;               // 16B chunks per row
#pragma unroll
        for (int u = 0; u < (128 * CH) / 256; ++u) {
            int idx = tid + u * 256;
            int r = idx / CH;
            int c8 = (idx % CH) * 8;
            int gc = n0 + r;
            uint4 v = make_uint4(0, 0, 0, 0);
            if (gc < NC) v = *(const uint4*)(Wt + (size_t)gc * K + c8);
            *(uint4*)&Bs[r * ST + c8] = v;
        }
        __syncthreads();

        float acc[2][8][4];
#pragma unroll
        for (int q = 0; q < 2; ++q)
#pragma unroll
            for (int nt = 0; nt < 8; ++nt)
#pragma unroll
                for (int j = 0; j < 4; ++j) acc[q][nt][j] = 0.f;

#pragma unroll
        for (int kc = 0; kc < K / 16; ++kc) {
            int kk = kc * 16;
            uint32_t a[2][4];
#pragma unroll
            for (int q = 0; q < 2; ++q) {
                int rb = wm * 32 + q * 16;
                a[q][0] = *(const uint32_t*)&As[(rb + gid) * ST + kk + tig * 2];
                a[q][1] = *(const uint32_t*)&As[(rb + gid + 8) * ST + kk + tig * 2];
                a[q][2] = *(const uint32_t*)&As[(rb + gid) * ST + kk + 8 + tig * 2];
                a[q][3] = *(const uint32_t*)&As[(rb + gid + 8) * ST + kk + 8 + tig * 2];
            }
            uint32_t b[8][2];
#pragma unroll
            for (int nt = 0; nt < 8; ++nt) {
                int col = wn * 64 + nt * 8 + gid;
                b[nt][0] = *(const uint32_t*)&Bs[col * ST + kk + tig * 2];
                b[nt][1] = *(const uint32_t*)&Bs[col * ST + kk + 8 + tig * 2];
            }
#pragma unroll
            for (int q = 0; q < 2; ++q)
#pragma unroll
                for (int nt = 0; nt < 8; ++nt)
                    mma_f16(acc[q][nt], a[q][0], a[q][1], a[q][2], a[q][3],
                            b[nt][0], b[nt][1]);
        }

        // epilogue for this tile
#pragma unroll
        for (int q = 0; q < 2; ++q) {
            int r0 = m0 + wm * 32 + q * 16 + gid;
#pragma unroll
            for (int nt = 0; nt < 8; ++nt) {
                int c = n0 + wn * 64 + nt * 8 + tig * 2;
                if (c >= NC) continue;
                float b0v = biassm[c], b1v = biassm[c + 1];
                if (r0 < M)      store2(r0,     c, acc[q][nt][0] + b0v, acc[q][nt][1] + b1v);
                if (r0 + 8 < M)  store2(r0 + 8, c, acc[q][nt][2] + b0v, acc[q][nt][3] + b1v);
            }
        }
        __syncthreads();   // Bs reused next tile
    }
}

// ---------------- attention: warp/node online softmax, 4-edge batches, fp16 kv ----------------
__device__ __forceinline__ float4 h4_to_f4(uint2 u) {
    __half2 h0 = *reinterpret_cast<__half2*>(&u.x);
    __half2 h1 = *reinterpret_cast<__half2*>(&u.y);
    float2 f0 = __half22float2(h0);
    float2 f1 = __half22float2(h1);
    return make_float4(f0.x, f0.y, f1.x, f1.y);
}

__global__ void k_attn(int n) {
    int gw = (blockIdx.x * blockDim.x + threadIdx.x) >> 5;
    if (gw >= n) return;
    int lane = threadIdx.x & 31;
    int l = lane & 7;
    int off = (lane >> 3) * 32 + l * 4;
    const float scale = 0.17677669529663687f;  // 1/sqrt(32)

    float4 q = *(const float4*)(g_qs + (size_t)gw * QS_STRIDE + off);
    float m = -1e30f, ssum = 0.f;
    float ax = 0.f, ay = 0.f, az = 0.f, aw = 0.f;

    int beg = g_rowptr[gw], end = g_rowptr[gw + 1];

    for (int base = beg; base < end; base += 4) {
        int cnt = end - base; if (cnt > 4) cnt = 4;
        int s[4];
#pragma unroll
        for (int j = 0; j < 4; ++j)
            s[j] = __ldg(g_esrc + base + ((j < cnt) ? j : 0));

        float4 kk[4], vv[4];
#pragma unroll
        for (int j = 0; j < 4; ++j) {
            const __half* kb = g_kv + (size_t)s[j] * KV_STRIDE + off;
            uint2 ku = *(const uint2*)kb;
            uint2 vu = *(const uint2*)(kb + 128);
            kk[j] = h4_to_f4(ku);
            vv[j] = h4_to_f4(vu);
        }

        float d[4];
#pragma unroll
        for (int j = 0; j < 4; ++j)
            d[j] = q.x * kk[j].x + q.y * kk[j].y + q.z * kk[j].z + q.w * kk[j].w;
#pragma unroll
        for (int st = 1; st <= 4; st <<= 1)
#pragma unroll
            for (int j = 0; j < 4; ++j)
                d[j] += __shfl_xor_sync(0xffffffffu, d[j], st);

        float a[4];
#pragma unroll
        for (int j = 0; j < 4; ++j)
            a[j] = (j < cnt) ? d[j] * scale : -1e30f;

        float bm = fmaxf(fmaxf(a[0], a[1]), fmaxf(a[2], a[3]));
        float mn = fmaxf(m, bm);
        float sc = __expf(m - mn);
        float p[4];
#pragma unroll
        for (int j = 0; j < 4; ++j) p[j] = __expf(a[j] - mn);

        ssum = ssum * sc + p[0] + p[1] + p[2] + p[3];
        ax = ax * sc + p[0] * vv[0].x + p[1] * vv[1].x + p[2] * vv[2].x + p[3] * vv[3].x;
        ay = ay * sc + p[0] * vv[0].y + p[1] * vv[1].y + p[2] * vv[2].y + p[3] * vv[3].y;
        az = az * sc + p[0] * vv[0].z + p[1] * vv[1].z + p[2] * vv[2].z + p[3] * vv[3].z;
        aw = aw * sc + p[0] * vv[0].w + p[1] * vv[1].w + p[2] * vv[2].w + p[3] * vv[3].w;
        m = mn;
    }

    float inv = (ssum > 0.f) ? (1.f / ssum) : 0.f;
    ax *= inv; ay *= inv; az *= inv; aw *= inv;

    // mean over 4 heads
    ax += __shfl_xor_sync(0xffffffffu, ax, 8);
    ay += __shfl_xor_sync(0xffffffffu, ay, 8);
    az += __shfl_xor_sync(0xffffffffu, az, 8);
    aw += __shfl_xor_sync(0xffffffffu, aw, 8);
    ax += __shfl_xor_sync(0xffffffffu, ax, 16);
    ay += __shfl_xor_sync(0xffffffffu, ay, 16);
    az += __shfl_xor_sync(0xffffffffu, az, 16);
    aw += __shfl_xor_sync(0xffffffffu, aw, 16);

    if (lane < 8) {
        float4 sk = *(const float4*)(g_qs + (size_t)gw * QS_STRIDE + 128 + l * 4);
        float4 o;
        o.x = fmaxf(ax * 0.25f + sk.x, 0.f);
        o.y = fmaxf(ay * 0.25f + sk.y, 0.f);
        o.z = fmaxf(az * 0.25f + sk.z, 0.f);
        o.w = fmaxf(aw * 0.25f + sk.w, 0.f);
        *(float4*)(g_h + (size_t)gw * 32 + l * 4) = o;
    }
}

// ---------------- output projection: out[n,16] = h[n,32] @ Wout + bout ----------------
__global__ void __launch_bounds__(256) k_outproj(const float* __restrict__ Wout,
                                                 const float* __restrict__ bout,
                                                 float* __restrict__ out, int n) {
    __shared__ float Hs[128 * 32];
    __shared__ float Ws[512];
    __shared__ float Bs2[16];
    int node0 = blockIdx.x * 128;
    for (int i = threadIdx.x; i < 512; i += 256) Ws[i] = Wout[i];
    if (threadIdx.x < 16) Bs2[threadIdx.x] = bout[threadIdx.x];
    for (int i = threadIdx.x; i < 128 * 32; i += 256) {
        int r = node0 + (i >> 5);
        Hs[i] = (r < n) ? g_h[(size_t)node0 * 32 + i] : 0.f;
    }
    __syncthreads();
#pragma unroll
    for (int t = 0; t < 8; ++t) {
        int oi = threadIdx.x + t * 256;
        int ln = oi >> 4;
        int j = oi & 15;
        int node = node0 + ln;
        if (node >= n) continue;
        float acc = Bs2[j];
#pragma unroll
        for (int k = 0; k < 32; ++k) acc += Hs[ln * 32 + k] * Ws[k * 16 + j];
        out[(size_t)node * 16 + j] = acc;
    }
}

// ---------------- launch ----------------
static cudaStream_t g_s2 = nullptr;
static cudaEvent_t g_evF = nullptr, g_evJ = nullptr;

extern "C" void kernel_launch(void* const* d_in, const int* in_sizes, int n_in,
                              void* d_out, int out_size) {
    if (!g_s2) {
        cudaStreamCreateWithFlags(&g_s2, cudaStreamNonBlocking);
        cudaEventCreateWithFlags(&g_evF, cudaEventDisableTiming);
        cudaEventCreateWithFlags(&g_evJ, cudaEventDisableTiming);
    }
    const float* x = (const float*)d_in[0];
    const int*   ei = (const int*)d_in[1];
    int n = in_sizes[0] / 128;
    int e = in_sizes[1] / 2;
    const int* srcp = ei;
    const int* dstp = ei + e;

    const int smem0 = 1792 + 2 * 128 * (128 + 8) * 2;   // K=128: ~71.5 KB
    const int smem1 = 1792 + 2 * 128 * (32 + 8) * 2;    // K=32:  ~21.8 KB
    cudaFuncSetAttribute(k_gemm<128>, cudaFuncAttributeMaxDynamicSharedMemorySize, smem0);
    cudaFuncSetAttribute(k_gemm<32>,  cudaFuncAttributeMaxDynamicSharedMemorySize, smem1);

    int nb = (n + 255) / 256;
    int eb = (e + 255) / 256;
    int sblocks = (n + SCAN_B - 1) / SCAN_B;
    int gemm_blocks = (n + 127) / 128;
    int attn_blocks = (n + 7) / 8;
    int pack_total = NC * 128 + NC * 32 + 2 * NC;

    // Fork: CSR build on side stream, overlapped with pack + layer-0 GEMM.
    cudaEventRecord(g_evF, 0);
    cudaStreamWaitEvent(g_s2, g_evF, 0);

    // main stream (submissions 1,4 keep gemm<128> in the profiled slot)
    k_pack_all<<<(pack_total + 255) / 256, 256>>>(
        (const float*)d_in[2],  (const float*)d_in[3],
        (const float*)d_in[4],  (const float*)d_in[5],
        (const float*)d_in[6],  (const float*)d_in[7],
        (const float*)d_in[8],  (const float*)d_in[9],
        (const float*)d_in[10], (const float*)d_in[11],
        (const float*)d_in[12], (const float*)d_in[13],
        (const float*)d_in[14], (const float*)d_in[15],
        (const float*)d_in[16], (const float*)d_in[17]);
    k_zero_cnt<<<nb, 256, 0, g_s2>>>(n);
    k_hist<<<eb, 256, 0, g_s2>>>(dstp, e);
    k_gemm<128><<<gemm_blocks, 256, smem0>>>(x, n);        // <- profiled slot (4th)
    k_scan1<<<sblocks, SCAN_B, 0, g_s2>>>(n);
    k_scan2<<<1, SCAN_B, 0, g_s2>>>(sblocks);
    k_scan3<<<sblocks, SCAN_B, 0, g_s2>>>(n);
    k_scatter<<<eb, 256, 0, g_s2>>>(srcp, dstp, e);
    cudaEventRecord(g_evJ, g_s2);
    cudaStreamWaitEvent(0, g_evJ, 0);                      // join before attention

    k_attn<<<attn_blocks, 256>>>(n);
    k_gemm<32><<<gemm_blocks, 256, smem1>>>(nullptr, n);
    k_attn<<<attn_blocks, 256>>>(n);
    k_outproj<<<(n + 127) / 128, 256>>>(
        (const float*)d_in[18], (const float*)d_in[19], (float*)d_out, n);
}